// round 3
// baseline (speedup 1.0000x reference)
#include <cuda_runtime.h>
#include <math.h>

#define B   32
#define H   1024
#define TZ  16
#define TU  128
#define E   512
#define V   32000
#define XD  2560      // E + 2H
#define G3  3072      // 3H
#define LN_EPS 1e-3f

// ----------------- static scratch (allocation-free) -----------------
__device__ float d_hproj_z[B * H];
__device__ float d_hproj_u[B * H];
__device__ float d_gpart  [B * H];
__device__ float d_scores_z[B * TZ];
__device__ float d_scores_u[B * TU];
__device__ float d_zc      [B * TZ];
__device__ float d_ctx_z[B * H];
__device__ float d_ctx_u[B * H];
__device__ float d_x  [B * XD];
__device__ float d_gi [B * G3];
__device__ float d_gh [B * G3];
__device__ float d_gru[B * H];
__device__ float d_gen[B * V];
__device__ float d_rmax[B];
__device__ float d_rsum[B];
__device__ float d_cp[B * TZ];

// ----------------- skinny proj: out[b][j] += sum_k in[b][k]*W[k*ldw+j] (+bias on y==0) ----
// grid(N/256, KSPLIT), 256 thr. K chunk must be multiple of 64.
__global__ void skinny_proj(const float* __restrict__ in, int K,
                            const float* __restrict__ W, int ldw,
                            const float* __restrict__ bias,
                            float* __restrict__ out, int N, int kchunk)
{
    int j  = blockIdx.x * 256 + threadIdx.x;
    int k0 = blockIdx.y * kchunk;
    int k1 = k0 + kchunk;
    float acc[B];
#pragma unroll
    for (int b = 0; b < B; b++) acc[b] = 0.f;
    __shared__ float xs[B][64];
    for (int kb = k0; kb < k1; kb += 64) {
        for (int e = threadIdx.x; e < B * 64; e += 256) {
            int bb = e >> 6, kk = e & 63;
            xs[bb][kk] = in[bb * K + kb + kk];
        }
        __syncthreads();
#pragma unroll 4
        for (int kk = 0; kk < 64; kk++) {
            float w = W[(kb + kk) * ldw + j];
#pragma unroll
            for (int b = 0; b < B; b++) acc[b] = fmaf(xs[b][kk], w, acc[b]);
        }
        __syncthreads();
    }
    float bv = (blockIdx.y == 0) ? bias[j] : 0.f;
    for (int b = 0; b < B; b++) atomicAdd(&out[b * N + j], acc[b] + bv);
}

// ----------------- fused energy GEMM + tanh + dot(v) -> scores -----------------
// A: [M][H] rows r=t*B+b. Wp: rows k -> Wp[k*H + n] (pointer pre-offset).
// scores[b*T+t] += sum_n tanh(A@Wp + addv[b][n]) * v[n]   (atomic over N-tiles)
#define BM 64
#define BN 64
#define BK 16
__global__ void energy_score(const float* __restrict__ A,
                             const float* __restrict__ Wp,
                             const float* __restrict__ addv,
                             const float* __restrict__ vvec,
                             float* __restrict__ out,
                             int M, int T)
{
    __shared__ float As[BK][BM];
    __shared__ float Bs[BK][BN];
    int row0 = blockIdx.y * BM, col0 = blockIdx.x * BN;
    int tx = threadIdx.x & 15, ty = threadIdx.x >> 4;
    float acc[4][4] = {};
    for (int k0 = 0; k0 < H; k0 += BK) {
        for (int e = threadIdx.x; e < BM * BK; e += 256) {
            int m = e / BK, kk = e % BK;
            As[kk][m] = A[(row0 + m) * H + k0 + kk];
        }
        for (int e = threadIdx.x; e < BN * BK; e += 256) {
            int kk = e / BN, n = e % BN;
            Bs[kk][n] = Wp[(k0 + kk) * H + col0 + n];
        }
        __syncthreads();
#pragma unroll
        for (int kk = 0; kk < BK; kk++) {
            float a[4], bb[4];
#pragma unroll
            for (int i = 0; i < 4; i++) a[i] = As[kk][ty * 4 + i];
#pragma unroll
            for (int j = 0; j < 4; j++) bb[j] = Bs[kk][tx * 4 + j];
#pragma unroll
            for (int i = 0; i < 4; i++)
#pragma unroll
                for (int j = 0; j < 4; j++) acc[i][j] = fmaf(a[i], bb[j], acc[i][j]);
        }
        __syncthreads();
    }
    __shared__ float red[BM][16];
#pragma unroll
    for (int i = 0; i < 4; i++) {
        int r = row0 + ty * 4 + i;
        int bidx = r % B;
        float s = 0.f;
#pragma unroll
        for (int j = 0; j < 4; j++) {
            int n = col0 + tx * 4 + j;
            float ev = tanhf(acc[i][j] + addv[bidx * H + n]);
            s = fmaf(ev, vvec[n], s);
        }
        red[ty * 4 + i][tx] = s;
    }
    __syncthreads();
    for (int lr = threadIdx.x; lr < BM; lr += 256) {
        float t = 0.f;
#pragma unroll
        for (int c = 0; c < 16; c++) t += red[lr][c];
        int r = row0 + lr;
        atomicAdd(&out[(r % B) * T + (r / B)], t);
    }
}

// ----------------- softmax over scores + weighted context -----------------
__global__ void attn_ctx(const float* __restrict__ scores,
                         const float* __restrict__ enc,
                         float* __restrict__ ctx, int T)
{
    int b = blockIdx.x, tid = threadIdx.x;
    __shared__ float w[TU];
    __shared__ float inv_s;
    if (tid < T) w[tid] = scores[b * T + tid];
    __syncthreads();
    if (tid == 0) {
        float mx = -1e30f;
        for (int t = 0; t < T; t++) mx = fmaxf(mx, w[t]);
        float s = 0.f;
        for (int t = 0; t < T; t++) { float e = expf(w[t] - mx); w[t] = e; s += e; }
        inv_s = 1.f / s;
    }
    __syncthreads();
    int j = blockIdx.y * 256 + tid;
    float acc = 0.f;
    for (int t = 0; t < T; t++) acc = fmaf(w[t], enc[(t * B + b) * H + j], acc);
    ctx[b * H + j] = acc * inv_s;
}

// ----------------- build x = [ctx_z | ctx_u | emb[m_t]] -----------------
__global__ void build_x(const float* __restrict__ cz, const float* __restrict__ cu,
                        const float* __restrict__ emb, const int* __restrict__ mt,
                        float* __restrict__ x)
{
    int idx = blockIdx.x * 256 + threadIdx.x;
    if (idx >= B * XD) return;
    int b = idx / XD, k = idx % XD;
    float vl;
    if (k < H)            vl = cz[b * H + k];
    else if (k < 2 * H)   vl = cu[b * H + (k - H)];
    else                  vl = emb[(long)mt[b] * E + (k - 2 * H)];
    x[idx] = vl;
}

// ----------------- row-dot GEMM: out[b][j] = sum_k in[b][k]*W[j*K+k] + bias[j] ----
// tile: 16 j per block, all 32 b. grid(N/16), 256 thr, 2 outputs/thread.
__global__ void rowdot(const float* __restrict__ in, int K,
                       const float* __restrict__ W,
                       const float* __restrict__ bias,
                       float* __restrict__ out, int N)
{
    int j0 = blockIdx.x * 16;
    __shared__ float Ws[16][65];
    __shared__ float Xs[B][64];
    int tid = threadIdx.x;
    int b1 = tid >> 4,        j1 = tid & 15;
    int b2 = (tid + 256) >> 4, j2 = tid & 15;
    float a1 = 0.f, a2 = 0.f;
    for (int k0 = 0; k0 < K; k0 += 64) {
        for (int e = tid; e < 16 * 64; e += 256) {
            int jl = e >> 6, kk = e & 63;
            Ws[jl][kk] = W[(j0 + jl) * K + k0 + kk];
        }
        for (int e = tid; e < B * 64; e += 256) {
            int bb = e >> 6, kk = e & 63;
            Xs[bb][kk] = in[bb * K + k0 + kk];
        }
        __syncthreads();
#pragma unroll 8
        for (int kk = 0; kk < 64; kk++) {
            a1 = fmaf(Xs[b1][kk], Ws[j1][kk], a1);
            a2 = fmaf(Xs[b2][kk], Ws[j2][kk], a2);
        }
        __syncthreads();
    }
    out[b1 * N + j0 + j1] = a1 + bias[j0 + j1];
    out[b2 * N + j0 + j2] = a2 + bias[j0 + j2];
}

// ----------------- GRU gates + layernorm (ddof=1, (sigma+eps) denom) -----------------
__global__ void gru_ln(const float* __restrict__ gi, const float* __restrict__ gh,
                       const float* __restrict__ h,
                       const float* __restrict__ lna, const float* __restrict__ lnb,
                       float* __restrict__ hnew_out, float* __restrict__ gru_out)
{
    int b = blockIdx.x, j = threadIdx.x;   // 1024 threads
    float ir = gi[b * G3 + j], iz = gi[b * G3 + H + j], inn = gi[b * G3 + 2 * H + j];
    float hr = gh[b * G3 + j], hz = gh[b * G3 + H + j], hn  = gh[b * G3 + 2 * H + j];
    float r  = 1.f / (1.f + expf(-(ir + hr)));
    float zg = 1.f / (1.f + expf(-(iz + hz)));
    float n  = tanhf(inn + r * hn);
    float hv = h[b * H + j];
    float hnew = (1.f - zg) * n + zg * hv;
    hnew_out[b * H + j] = hnew;
    __shared__ float sh[1024];
    sh[j] = hnew; __syncthreads();
    for (int s = 512; s > 0; s >>= 1) { if (j < s) sh[j] += sh[j + s]; __syncthreads(); }
    float mu = sh[0] * (1.f / H); __syncthreads();
    float d = hnew - mu;
    sh[j] = d * d; __syncthreads();
    for (int s = 512; s > 0; s >>= 1) { if (j < s) sh[j] += sh[j + s]; __syncthreads(); }
    float sigma = sqrtf(sh[0] / (float)(H - 1));
    gru_out[b * H + j] = d / (sigma + LN_EPS) * lna[j] + lnb[j];
}

// ----------------- vocab projection: gen[b][v] += sum_k g[b][k]*W_proj[k*V+v] ------
// grid(V/256, 4 ksplit), 256 thr.
__global__ void gen_gemm(const float* __restrict__ g, const float* __restrict__ Wp,
                         float* __restrict__ gen)
{
    int v = blockIdx.x * 256 + threadIdx.x;
    int kbase = blockIdx.y * 256;
    __shared__ float gs[B][256];
    for (int e = threadIdx.x; e < B * 256; e += 256) {
        int bb = e >> 8, kk = e & 255;
        gs[bb][kk] = g[bb * H + kbase + kk];
    }
    __syncthreads();
    float acc[B] = {};
#pragma unroll 4
    for (int kk = 0; kk < 256; kk++) {
        float w = Wp[(long)(kbase + kk) * V + v];
#pragma unroll
        for (int b = 0; b < B; b++) acc[b] = fmaf(gs[b][kk], w, acc[b]);
    }
#pragma unroll
    for (int b = 0; b < B; b++) atomicAdd(&gen[b * V + v], acc[b]);
}

// ----------------- softmax stats over [gen | zc] per b -----------------
__global__ void softmax_stats(const float* __restrict__ gen, const float* __restrict__ bproj,
                              const float* __restrict__ zc,  const float* __restrict__ bv1,
                              float* __restrict__ rmax, float* __restrict__ rsum,
                              float* __restrict__ cp)
{
    int b = blockIdx.x, tid = threadIdx.x;  // 256 thr
    float bz = bv1[0];
    float mx = -1e30f;
    for (int v = tid; v < V; v += 256) mx = fmaxf(mx, gen[b * V + v] + bproj[v]);
    if (tid < TZ) mx = fmaxf(mx, zc[b * TZ + tid] + bz);
    __shared__ float sh[256];
    sh[tid] = mx; __syncthreads();
    for (int s = 128; s > 0; s >>= 1) { if (tid < s) sh[tid] = fmaxf(sh[tid], sh[tid + s]); __syncthreads(); }
    mx = sh[0]; __syncthreads();
    float s = 0.f;
    for (int v = tid; v < V; v += 256) s += __expf(gen[b * V + v] + bproj[v] - mx);
    if (tid < TZ) s += __expf(zc[b * TZ + tid] + bz - mx);
    sh[tid] = s; __syncthreads();
    for (int st = 128; st > 0; st >>= 1) { if (tid < st) sh[tid] += sh[tid + st]; __syncthreads(); }
    s = sh[0];
    if (tid == 0) { rmax[b] = mx; rsum[b] = s; }
    if (tid < TZ) cp[b * TZ + tid] = __expf(zc[b * TZ + tid] + bz - mx) / s;
}

// ----------------- final: proba = gen_p + mask*(copy_p @ pz) -----------------
__global__ void final_combine(const float* __restrict__ gen, const float* __restrict__ bproj,
                              const float* __restrict__ pz,
                              const float* __restrict__ rmax, const float* __restrict__ rsum,
                              const float* __restrict__ cp,
                              float* __restrict__ out)
{
    int b = blockIdx.y;
    int v = blockIdx.x * 256 + threadIdx.x;
    __shared__ float cps[TZ];
    __shared__ float st[2];
    if (threadIdx.x < TZ) cps[threadIdx.x] = cp[b * TZ + threadIdx.x];
    if (threadIdx.x == 0) { st[0] = rmax[b]; st[1] = 1.f / rsum[b]; }
    __syncthreads();
    float gp = __expf(gen[b * V + v] + bproj[v] - st[0]) * st[1];
    float acc = 0.f;
#pragma unroll
    for (int t = 0; t < TZ; t++) acc = fmaf(cps[t], pz[(long)(t * B + b) * V + v], acc);
    out[b * V + v] = gp + (v >= 4 ? acc : 0.f);
}

// ===================================================================
extern "C" void kernel_launch(void* const* d_in, const int* in_sizes, int n_in,
                              void* d_out, int out_size)
{
    const float* z_enc  = (const float*)d_in[0];
    const float* pz     = (const float*)d_in[1];
    const float* u_enc  = (const float*)d_in[2];
    const int*   mt     = (const int*)  d_in[3];
    const float* h      = (const float*)d_in[4];
    const float* emb    = (const float*)d_in[5];
    const float* Wa_z   = (const float*)d_in[6];
    const float* ba_z   = (const float*)d_in[7];
    const float* v_z    = (const float*)d_in[8];
    const float* Wa_u   = (const float*)d_in[9];
    const float* ba_u   = (const float*)d_in[10];
    const float* v_u    = (const float*)d_in[11];
    const float* W_ih   = (const float*)d_in[12];
    const float* W_hh   = (const float*)d_in[13];
    const float* b_ih   = (const float*)d_in[14];
    const float* b_hh   = (const float*)d_in[15];
    const float* ln_a   = (const float*)d_in[16];
    const float* ln_b   = (const float*)d_in[17];
    const float* W_proj = (const float*)d_in[18];
    const float* b_proj = (const float*)d_in[19];
    const float* W_c    = (const float*)d_in[20];
    const float* b_c    = (const float*)d_in[21];
    const float* W_v1   = (const float*)d_in[22];
    const float* b_v1   = (const float*)d_in[23];
    float* out = (float*)d_out;

    float *hpz, *hpu, *gpart, *sz, *su, *zcb, *cz, *cu, *xb, *gib, *ghb, *grub, *genb, *rmx, *rsm, *cpb;
    cudaGetSymbolAddress((void**)&hpz,  d_hproj_z);
    cudaGetSymbolAddress((void**)&hpu,  d_hproj_u);
    cudaGetSymbolAddress((void**)&gpart,d_gpart);
    cudaGetSymbolAddress((void**)&sz,   d_scores_z);
    cudaGetSymbolAddress((void**)&su,   d_scores_u);
    cudaGetSymbolAddress((void**)&zcb,  d_zc);
    cudaGetSymbolAddress((void**)&cz,   d_ctx_z);
    cudaGetSymbolAddress((void**)&cu,   d_ctx_u);
    cudaGetSymbolAddress((void**)&xb,   d_x);
    cudaGetSymbolAddress((void**)&gib,  d_gi);
    cudaGetSymbolAddress((void**)&ghb,  d_gh);
    cudaGetSymbolAddress((void**)&grub, d_gru);
    cudaGetSymbolAddress((void**)&genb, d_gen);
    cudaGetSymbolAddress((void**)&rmx,  d_rmax);
    cudaGetSymbolAddress((void**)&rsm,  d_rsum);
    cudaGetSymbolAddress((void**)&cpb,  d_cp);

    // zero atomic accumulators
    cudaMemsetAsync(hpz,  0, B * H  * sizeof(float));
    cudaMemsetAsync(hpu,  0, B * H  * sizeof(float));
    cudaMemsetAsync(gpart,0, B * H  * sizeof(float));
    cudaMemsetAsync(sz,   0, B * TZ * sizeof(float));
    cudaMemsetAsync(su,   0, B * TU * sizeof(float));
    cudaMemsetAsync(zcb,  0, B * TZ * sizeof(float));
    cudaMemsetAsync(genb, 0, B * V  * sizeof(float));

    // hidden-part of attention energies:  h @ Wa[:H] + ba
    skinny_proj<<<dim3(4, 4), 256>>>(h, H, Wa_z, H, ba_z, hpz, H, 256);
    skinny_proj<<<dim3(4, 4), 256>>>(h, H, Wa_u, H, ba_u, hpu, H, 256);

    // enc-part + tanh + dot(v) -> scores
    energy_score<<<dim3(16, (TZ * B) / BM), 256>>>(z_enc, Wa_z + H * H, hpz, v_z, sz, TZ * B, TZ);
    energy_score<<<dim3(16, (TU * B) / BM), 256>>>(u_enc, Wa_u + H * H, hpu, v_u, su, TU * B, TU);

    // softmax + context
    attn_ctx<<<dim3(B, 4), 256>>>(sz, z_enc, cz, TZ);
    attn_ctx<<<dim3(B, 4), 256>>>(su, u_enc, cu, TU);

    // x = [ctx_z | ctx_u | emb gather]
    build_x<<<(B * XD + 255) / 256, 256>>>(cz, cu, emb, mt, xb);

    // GRU gates
    rowdot<<<G3 / 16, 256>>>(xb, XD, W_ih, b_ih, gib, G3);
    rowdot<<<G3 / 16, 256>>>(h,  H,  W_hh, b_hh, ghb, G3);

    // gates + layernorm; writes h_new into the tail of d_out
    gru_ln<<<B, 1024>>>(gib, ghb, h, ln_a, ln_b, out + (long)B * V, grub);

    // copy branch: gru-part of W_c, then fused z_enc@W_c[:H] + tanh + dot(W_v1)
    skinny_proj<<<dim3(4, 4), 256>>>(grub, H, W_c + H * H, H, b_c, gpart, H, 256);
    energy_score<<<dim3(16, (TZ * B) / BM), 256>>>(z_enc, W_c, gpart, W_v1, zcb, TZ * B, TZ);

    // vocab projection
    gen_gemm<<<dim3(V / 256, 4), 256>>>(grub, W_proj, genb);

    // joint softmax over [gen | zc], then combine with copy distribution
    softmax_stats<<<B, 256>>>(genb, b_proj, zcb, b_v1, rmx, rsm, cpb);
    final_combine<<<dim3(V / 256, B), 256>>>(genb, b_proj, pz, rmx, rsm, cpb, out);

    (void)in_sizes; (void)n_in; (void)out_size;
}

// round 4
// speedup vs baseline: 2.4781x; 2.4781x over previous
#include <cuda_runtime.h>
#include <cuda_bf16.h>
#include <math.h>

#define B   32
#define H   1024
#define TZ  16
#define TU  128
#define E   512
#define V   32000
#define XD  2560
#define G3  3072
#define LN_EPS 1e-3f

__device__ float d_hproj_z[B * H];
__device__ float d_hproj_u[B * H];
__device__ float d_gpart  [B * H];
__device__ float d_scores_z[B * TZ];
__device__ float d_scores_u[B * TU];
__device__ float d_zc      [B * TZ];
__device__ float d_ctx_z[B * H];
__device__ float d_ctx_u[B * H];
__device__ float d_x  [B * XD];
__device__ float d_gi [B * G3];
__device__ float d_gh [B * G3];
__device__ float d_gru[B * H];
__device__ float d_gen[B * V];
__device__ float d_rsum[B];
__device__ float d_cp[B * TZ];
__device__ __align__(16) __nv_bfloat16 d_uAh[TU * B * H];
__device__ __align__(16) __nv_bfloat16 d_uAl[TU * B * H];
__device__ __align__(16) __nv_bfloat16 d_zAh[TZ * B * H];
__device__ __align__(16) __nv_bfloat16 d_zAl[TZ * B * H];
__device__ __align__(16) __nv_bfloat16 d_WuTh[H * H];
__device__ __align__(16) __nv_bfloat16 d_WuTl[H * H];
__device__ __align__(16) __nv_bfloat16 d_WzTh[H * H];
__device__ __align__(16) __nv_bfloat16 d_WzTl[H * H];
__device__ __align__(16) __nv_bfloat16 d_WcTh[H * H];
__device__ __align__(16) __nv_bfloat16 d_WcTl[H * H];

__device__ __forceinline__ float fast_tanh(float x)
{
    float xc = fminf(fmaxf(x, -7.90531f), 7.90531f);
    float x2 = xc * xc;
    float p = fmaf(x2, -2.76076847742355e-16f, 2.00018790482477e-13f);
    p = fmaf(x2, p, -8.60467152213735e-11f);
    p = fmaf(x2, p,  5.12229709037114e-08f);
    p = fmaf(x2, p,  1.48572235717979e-05f);
    p = fmaf(x2, p,  6.37261928875436e-04f);
    p = fmaf(x2, p,  4.89352455891786e-03f);
    p = xc * p;
    float q = fmaf(x2, 1.19825839466702e-06f, 1.18534705686654e-04f);
    q = fmaf(x2, q, 2.26843463243900e-03f);
    q = fmaf(x2, q, 4.89352518554385e-03f);
    return __fdividef(p, q);
}

__global__ void split_bf16(const float* __restrict__ x,
                           __nv_bfloat16* __restrict__ hi,
                           __nv_bfloat16* __restrict__ lo, int n)
{
    int i = blockIdx.x * 256 + threadIdx.x;
    if (i >= n) return;
    float v = x[i];
    __nv_bfloat16 h = __float2bfloat16(v);
    hi[i] = h;
    lo[i] = __float2bfloat16(v - __bfloat162float(h));
}

__global__ void transpose_split(const float* __restrict__ W, int ldw,
                                __nv_bfloat16* __restrict__ Th,
                                __nv_bfloat16* __restrict__ Tl)
{
    __shared__ float tile[32][33];
    int k0 = blockIdx.x * 32, n0 = blockIdx.y * 32;
    int tx = threadIdx.x & 31, ty = threadIdx.x >> 5;
    for (int i = ty; i < 32; i += 8)
        tile[i][tx] = W[(size_t)(k0 + i) * ldw + n0 + tx];
    __syncthreads();
    for (int i = ty; i < 32; i += 8) {
        float v = tile[tx][i];
        __nv_bfloat16 h = __float2bfloat16(v);
        Th[(size_t)(n0 + i) * H + k0 + tx] = h;
        Tl[(size_t)(n0 + i) * H + k0 + tx] = __float2bfloat16(v - __bfloat162float(h));
    }
}

__device__ __forceinline__ void mma16816(float* c, const unsigned* a, const unsigned* b)
{
    asm volatile(
        "mma.sync.aligned.m16n8k16.row.col.f32.bf16.bf16.f32 "
        "{%0,%1,%2,%3}, {%4,%5,%6,%7}, {%8,%9}, {%0,%1,%2,%3};"
        : "+f"(c[0]), "+f"(c[1]), "+f"(c[2]), "+f"(c[3])
        : "r"(a[0]), "r"(a[1]), "r"(a[2]), "r"(a[3]), "r"(b[0]), "r"(b[1]));
}

// scores[b,t] += sum_n tanh((A@Wt^T)[r,n] + addv[b,n]) * v[n] ; r=t*B+b
template<int BM, int BN, int WM, int WN>
__global__ void __launch_bounds__(WM * WN * 32)
energy_mma(const __nv_bfloat16* __restrict__ Ah, const __nv_bfloat16* __restrict__ Al,
           const __nv_bfloat16* __restrict__ Wh, const __nv_bfloat16* __restrict__ Wl,
           const float* __restrict__ addv, const float* __restrict__ vvec,
           float* __restrict__ out, int T)
{
    constexpr int THREADS = WM * WN * 32;
    constexpr int WTN = BN / WN;
    constexpr int NT  = WTN / 8;
    constexpr int SKW = 20;
    __shared__ unsigned sAh[BM * SKW], sAl[BM * SKW];
    __shared__ unsigned sBh[BN * SKW], sBl[BN * SKW];
    int tid = threadIdx.x, wid = tid >> 5, lane = tid & 31;
    int wm = wid / WN, wn = wid % WN;
    int row0 = blockIdx.y * BM, col0 = blockIdx.x * BN;
    int l4 = lane >> 2, lm = lane & 3;

    float c[2][NT][4];
#pragma unroll
    for (int mt = 0; mt < 2; mt++)
#pragma unroll
        for (int nt = 0; nt < NT; nt++)
#pragma unroll
            for (int e = 0; e < 4; e++) c[mt][nt][e] = 0.f;

    for (int k0 = 0; k0 < H; k0 += 32) {
        for (int i = tid; i < BM * 4; i += THREADS) {
            int m = i >> 2, q = i & 3;
            size_t off = (size_t)(row0 + m) * H + k0 + q * 8;
            *(uint4*)&sAh[m * SKW + q * 4] = *(const uint4*)(Ah + off);
            *(uint4*)&sAl[m * SKW + q * 4] = *(const uint4*)(Al + off);
        }
        for (int i = tid; i < BN * 4; i += THREADS) {
            int n = i >> 2, q = i & 3;
            size_t off = (size_t)(col0 + n) * H + k0 + q * 8;
            *(uint4*)&sBh[n * SKW + q * 4] = *(const uint4*)(Wh + off);
            *(uint4*)&sBl[n * SKW + q * 4] = *(const uint4*)(Wl + off);
        }
        __syncthreads();
#pragma unroll
        for (int ks = 0; ks < 2; ks++) {
            int kw = ks * 8 + lm;
            unsigned ah[2][4], al[2][4];
#pragma unroll
            for (int mt = 0; mt < 2; mt++) {
                int r = wm * 32 + mt * 16 + l4;
                ah[mt][0] = sAh[r * SKW + kw];       ah[mt][1] = sAh[(r + 8) * SKW + kw];
                ah[mt][2] = sAh[r * SKW + kw + 4];   ah[mt][3] = sAh[(r + 8) * SKW + kw + 4];
                al[mt][0] = sAl[r * SKW + kw];       al[mt][1] = sAl[(r + 8) * SKW + kw];
                al[mt][2] = sAl[r * SKW + kw + 4];   al[mt][3] = sAl[(r + 8) * SKW + kw + 4];
            }
#pragma unroll
            for (int nt = 0; nt < NT; nt++) {
                int cn = wn * WTN + nt * 8 + l4;
                unsigned bh[2] = { sBh[cn * SKW + kw], sBh[cn * SKW + kw + 4] };
                unsigned bl[2] = { sBl[cn * SKW + kw], sBl[cn * SKW + kw + 4] };
#pragma unroll
                for (int mt = 0; mt < 2; mt++) {
                    mma16816(c[mt][nt], ah[mt], bh);
                    mma16816(c[mt][nt], ah[mt], bl);
                    mma16816(c[mt][nt], al[mt], bh);
                }
            }
        }
        __syncthreads();
    }
#pragma unroll
    for (int mt = 0; mt < 2; mt++)
#pragma unroll
        for (int half = 0; half < 2; half++) {
            int row = row0 + wm * 32 + mt * 16 + l4 + half * 8;
            int b = row & 31, t = row >> 5;
            float s = 0.f;
#pragma unroll
            for (int nt = 0; nt < NT; nt++) {
                int n0 = col0 + wn * WTN + nt * 8 + lm * 2;
                float e0 = fast_tanh(c[mt][nt][half * 2 + 0] + addv[b * H + n0]);
                float e1 = fast_tanh(c[mt][nt][half * 2 + 1] + addv[b * H + n0 + 1]);
                s = fmaf(e0, vvec[n0], s);
                s = fmaf(e1, vvec[n0 + 1], s);
            }
            s += __shfl_xor_sync(0xffffffff, s, 1);
            s += __shfl_xor_sync(0xffffffff, s, 2);
            if (lm == 0) atomicAdd(&out[b * T + t], s);
        }
}

// out[b][j] += sum_k x[b][k]*W(k,j) (+bias on y==0). KMAJOR: W[k*ldw+j], else W[j*ldw+k].
template<bool KMAJOR>
__global__ void __launch_bounds__(128)
small_gemm(const float* __restrict__ x, int ldx,
           const float* __restrict__ W, int ldw,
           const float* __restrict__ bias,
           float* __restrict__ out, int N, int kchunk)
{
    __shared__ float xs[32][33];
    __shared__ float Ws[32 * 65];
    int tid = threadIdx.x, tj = tid & 15, tb = tid >> 4;
    int j0 = blockIdx.x * 64;
    int kbeg = blockIdx.y * kchunk, kend = kbeg + kchunk;
    float acc[4][4] = {};
    for (int k0 = kbeg; k0 < kend; k0 += 32) {
        for (int i = tid; i < 256; i += 128) {
            int bb = i >> 3, q = i & 7;
            float4 vv = *(const float4*)&x[(size_t)bb * ldx + k0 + q * 4];
            xs[bb][q * 4 + 0] = vv.x; xs[bb][q * 4 + 1] = vv.y;
            xs[bb][q * 4 + 2] = vv.z; xs[bb][q * 4 + 3] = vv.w;
        }
        if (KMAJOR) {
            for (int i = tid; i < 512; i += 128) {
                int kk = i >> 4, jq = i & 15;
                float4 vv = *(const float4*)&W[(size_t)(k0 + kk) * ldw + j0 + jq * 4];
                Ws[kk * 65 + jq * 4 + 0] = vv.x; Ws[kk * 65 + jq * 4 + 1] = vv.y;
                Ws[kk * 65 + jq * 4 + 2] = vv.z; Ws[kk * 65 + jq * 4 + 3] = vv.w;
            }
        } else {
            for (int i = tid; i < 512; i += 128) {
                int j = i >> 3, q = i & 7;
                float4 vv = *(const float4*)&W[(size_t)(j0 + j) * ldw + k0 + q * 4];
                Ws[(q * 4 + 0) * 65 + j] = vv.x; Ws[(q * 4 + 1) * 65 + j] = vv.y;
                Ws[(q * 4 + 2) * 65 + j] = vv.z; Ws[(q * 4 + 3) * 65 + j] = vv.w;
            }
        }
        __syncthreads();
#pragma unroll 8
        for (int kk = 0; kk < 32; kk++) {
            float a[4], w[4];
#pragma unroll
            for (int i = 0; i < 4; i++) a[i] = xs[tb * 4 + i][kk];
#pragma unroll
            for (int j = 0; j < 4; j++) w[j] = Ws[kk * 65 + tj * 4 + j];
#pragma unroll
            for (int i = 0; i < 4; i++)
#pragma unroll
                for (int j = 0; j < 4; j++) acc[i][j] = fmaf(a[i], w[j], acc[i][j]);
        }
        __syncthreads();
    }
#pragma unroll
    for (int i = 0; i < 4; i++)
#pragma unroll
        for (int j = 0; j < 4; j++) {
            int jj = j0 + tj * 4 + j;
            float v = acc[i][j] + ((blockIdx.y == 0) ? bias[jj] : 0.f);
            atomicAdd(&out[(tb * 4 + i) * N + jj], v);
        }
}

__global__ void attn_ctx(const float* __restrict__ scores,
                         const float* __restrict__ enc,
                         float* __restrict__ ctx, int T)
{
    int b = blockIdx.x, tid = threadIdx.x;
    __shared__ float w[TU];
    __shared__ float inv_s;
    if (tid < 32) {
        float m = -1e30f;
        for (int t = tid; t < T; t += 32) m = fmaxf(m, scores[b * T + t]);
#pragma unroll
        for (int o = 16; o > 0; o >>= 1) m = fmaxf(m, __shfl_xor_sync(0xffffffff, m, o));
        float s = 0.f;
        for (int t = tid; t < T; t += 32) {
            float e = __expf(scores[b * T + t] - m);
            w[t] = e; s += e;
        }
#pragma unroll
        for (int o = 16; o > 0; o >>= 1) s += __shfl_xor_sync(0xffffffff, s, o);
        if (tid == 0) inv_s = 1.f / s;
    }
    __syncthreads();
    int j = blockIdx.y * 256 + tid;
    float acc = 0.f;
    for (int t = 0; t < T; t++) acc = fmaf(w[t], enc[(size_t)(t * B + b) * H + j], acc);
    ctx[b * H + j] = acc * inv_s;
}

__global__ void build_x(const float* __restrict__ cz, const float* __restrict__ cu,
                        const float* __restrict__ emb, const int* __restrict__ mt,
                        float* __restrict__ x)
{
    int idx = blockIdx.x * 256 + threadIdx.x;
    if (idx >= B * XD) return;
    int b = idx / XD, k = idx % XD;
    float vl;
    if (k < H)           vl = cz[b * H + k];
    else if (k < 2 * H)  vl = cu[b * H + (k - H)];
    else                 vl = emb[(size_t)mt[b] * E + (k - 2 * H)];
    x[idx] = vl;
}

__global__ void gru_ln(const float* __restrict__ gi, const float* __restrict__ gh,
                       const float* __restrict__ h,
                       const float* __restrict__ lna, const float* __restrict__ lnb,
                       float* __restrict__ hnew_out, float* __restrict__ gru_out)
{
    int b = blockIdx.x, j = threadIdx.x;
    float ir = gi[b * G3 + j], iz = gi[b * G3 + H + j], inn = gi[b * G3 + 2 * H + j];
    float hr = gh[b * G3 + j], hz = gh[b * G3 + H + j], hn  = gh[b * G3 + 2 * H + j];
    float r  = 1.f / (1.f + __expf(-(ir + hr)));
    float zg = 1.f / (1.f + __expf(-(iz + hz)));
    float n  = fast_tanh(inn + r * hn);
    float hv = h[b * H + j];
    float hnew = (1.f - zg) * n + zg * hv;
    hnew_out[b * H + j] = hnew;
    __shared__ float sh[1024];
    sh[j] = hnew; __syncthreads();
    for (int s = 512; s > 0; s >>= 1) { if (j < s) sh[j] += sh[j + s]; __syncthreads(); }
    float mu = sh[0] * (1.f / H); __syncthreads();
    float d = hnew - mu;
    sh[j] = d * d; __syncthreads();
    for (int s = 512; s > 0; s >>= 1) { if (j < s) sh[j] += sh[j + s]; __syncthreads(); }
    float sigma = sqrtf(sh[0] / (float)(H - 1));
    gru_out[b * H + j] = d / (sigma + LN_EPS) * lna[j] + lnb[j];
}

__global__ void __launch_bounds__(128)
gen_gemm(const float* __restrict__ g, const float* __restrict__ Wp,
         const float* __restrict__ bproj, float* __restrict__ gen)
{
    __shared__ float gs[32][65];
    int tid = threadIdx.x, tv = tid & 31, tb = tid >> 5;
    int v0 = blockIdx.x * 128 + tv * 4;
    int b0 = tb * 8;
    int kbeg = blockIdx.y * 256;
    float acc[8][4] = {};
    for (int kb = 0; kb < 256; kb += 64) {
        for (int i = tid; i < 512; i += 128) {
            int bb = i >> 4, q = i & 15;
            float4 vv = *(const float4*)&g[(size_t)bb * H + kbeg + kb + q * 4];
            gs[bb][q * 4 + 0] = vv.x; gs[bb][q * 4 + 1] = vv.y;
            gs[bb][q * 4 + 2] = vv.z; gs[bb][q * 4 + 3] = vv.w;
        }
        __syncthreads();
#pragma unroll 4
        for (int kk = 0; kk < 64; kk++) {
            float4 w = *(const float4*)&Wp[(size_t)(kbeg + kb + kk) * V + v0];
            float a[8];
#pragma unroll
            for (int i = 0; i < 8; i++) a[i] = gs[b0 + i][kk];
#pragma unroll
            for (int i = 0; i < 8; i++) {
                acc[i][0] = fmaf(a[i], w.x, acc[i][0]);
                acc[i][1] = fmaf(a[i], w.y, acc[i][1]);
                acc[i][2] = fmaf(a[i], w.z, acc[i][2]);
                acc[i][3] = fmaf(a[i], w.w, acc[i][3]);
            }
        }
        __syncthreads();
    }
#pragma unroll
    for (int i = 0; i < 8; i++)
#pragma unroll
        for (int j = 0; j < 4; j++) {
            float v = acc[i][j] + ((blockIdx.y == 0) ? bproj[v0 + j] : 0.f);
            atomicAdd(&gen[(size_t)(b0 + i) * V + v0 + j], v);
        }
}

__global__ void softmax_stats(float* __restrict__ gen,
                              const float* __restrict__ zc, const float* __restrict__ bv1,
                              float* __restrict__ rsum_inv, float* __restrict__ cp)
{
    int b = blockIdx.x, tid = threadIdx.x;
    float bz = bv1[0];
    float mx = -1e30f;
    for (int v = tid; v < V; v += 256) mx = fmaxf(mx, gen[(size_t)b * V + v]);
    if (tid < TZ) mx = fmaxf(mx, zc[b * TZ + tid] + bz);
    __shared__ float sh[256];
    sh[tid] = mx; __syncthreads();
    for (int s = 128; s > 0; s >>= 1) { if (tid < s) sh[tid] = fmaxf(sh[tid], sh[tid + s]); __syncthreads(); }
    mx = sh[0]; __syncthreads();
    float s = 0.f;
    for (int v = tid; v < V; v += 256) {
        float e = __expf(gen[(size_t)b * V + v] - mx);
        gen[(size_t)b * V + v] = e;
        s += e;
    }
    if (tid < TZ) s += __expf(zc[b * TZ + tid] + bz - mx);
    sh[tid] = s; __syncthreads();
    for (int st = 128; st > 0; st >>= 1) { if (tid < st) sh[tid] += sh[tid + st]; __syncthreads(); }
    s = sh[0];
    if (tid == 0) rsum_inv[b] = 1.f / s;
    if (tid < TZ) cp[b * TZ + tid] = __expf(zc[b * TZ + tid] + bz - mx) / s;
}

__global__ void final_combine(const float* __restrict__ gen,
                              const float* __restrict__ pz,
                              const float* __restrict__ rsum_inv,
                              const float* __restrict__ cp,
                              float* __restrict__ out)
{
    int b = blockIdx.y;
    int v = blockIdx.x * 256 + threadIdx.x;
    __shared__ float cps[TZ];
    __shared__ float inv_s;
    if (threadIdx.x < TZ) cps[threadIdx.x] = cp[b * TZ + threadIdx.x];
    if (threadIdx.x == 0) inv_s = rsum_inv[b];
    __syncthreads();
    float gp = gen[(size_t)b * V + v] * inv_s;
    float acc = 0.f;
#pragma unroll
    for (int t = 0; t < TZ; t++) acc = fmaf(cps[t], pz[(size_t)(t * B + b) * V + v], acc);
    out[(size_t)b * V + v] = gp + (v >= 4 ? acc : 0.f);
}

extern "C" void kernel_launch(void* const* d_in, const int* in_sizes, int n_in,
                              void* d_out, int out_size)
{
    const float* z_enc  = (const float*)d_in[0];
    const float* pz     = (const float*)d_in[1];
    const float* u_enc  = (const float*)d_in[2];
    const int*   mt     = (const int*)  d_in[3];
    const float* h      = (const float*)d_in[4];
    const float* emb    = (const float*)d_in[5];
    const float* Wa_z   = (const float*)d_in[6];
    const float* ba_z   = (const float*)d_in[7];
    const float* v_z    = (const float*)d_in[8];
    const float* Wa_u   = (const float*)d_in[9];
    const float* ba_u   = (const float*)d_in[10];
    const float* v_u    = (const float*)d_in[11];
    const float* W_ih   = (const float*)d_in[12];
    const float* W_hh   = (const float*)d_in[13];
    const float* b_ih   = (const float*)d_in[14];
    const float* b_hh   = (const float*)d_in[15];
    const float* ln_a   = (const float*)d_in[16];
    const float* ln_b   = (const float*)d_in[17];
    const float* W_proj = (const float*)d_in[18];
    const float* b_proj = (const float*)d_in[19];
    const float* W_c    = (const float*)d_in[20];
    const float* b_c    = (const float*)d_in[21];
    const float* W_v1   = (const float*)d_in[22];
    const float* b_v1   = (const float*)d_in[23];
    float* out = (float*)d_out;

    float *hpz, *hpu, *gpart, *sz, *su, *zcb, *cz, *cu, *xb, *gib, *ghb, *grub, *genb, *rsm, *cpb;
    __nv_bfloat16 *uAh, *uAl, *zAh, *zAl, *WuTh, *WuTl, *WzTh, *WzTl, *WcTh, *WcTl;
    cudaGetSymbolAddress((void**)&hpz,  d_hproj_z);
    cudaGetSymbolAddress((void**)&hpu,  d_hproj_u);
    cudaGetSymbolAddress((void**)&gpart,d_gpart);
    cudaGetSymbolAddress((void**)&sz,   d_scores_z);
    cudaGetSymbolAddress((void**)&su,   d_scores_u);
    cudaGetSymbolAddress((void**)&zcb,  d_zc);
    cudaGetSymbolAddress((void**)&cz,   d_ctx_z);
    cudaGetSymbolAddress((void**)&cu,   d_ctx_u);
    cudaGetSymbolAddress((void**)&xb,   d_x);
    cudaGetSymbolAddress((void**)&gib,  d_gi);
    cudaGetSymbolAddress((void**)&ghb,  d_gh);
    cudaGetSymbolAddress((void**)&grub, d_gru);
    cudaGetSymbolAddress((void**)&genb, d_gen);
    cudaGetSymbolAddress((void**)&rsm,  d_rsum);
    cudaGetSymbolAddress((void**)&cpb,  d_cp);
    cudaGetSymbolAddress((void**)&uAh,  d_uAh);
    cudaGetSymbolAddress((void**)&uAl,  d_uAl);
    cudaGetSymbolAddress((void**)&zAh,  d_zAh);
    cudaGetSymbolAddress((void**)&zAl,  d_zAl);
    cudaGetSymbolAddress((void**)&WuTh, d_WuTh);
    cudaGetSymbolAddress((void**)&WuTl, d_WuTl);
    cudaGetSymbolAddress((void**)&WzTh, d_WzTh);
    cudaGetSymbolAddress((void**)&WzTl, d_WzTl);
    cudaGetSymbolAddress((void**)&WcTh, d_WcTh);
    cudaGetSymbolAddress((void**)&WcTl, d_WcTl);

    cudaMemsetAsync(hpz,  0, B * H  * sizeof(float));
    cudaMemsetAsync(hpu,  0, B * H  * sizeof(float));
    cudaMemsetAsync(gpart,0, B * H  * sizeof(float));
    cudaMemsetAsync(sz,   0, B * TZ * sizeof(float));
    cudaMemsetAsync(su,   0, B * TU * sizeof(float));
    cudaMemsetAsync(zcb,  0, B * TZ * sizeof(float));
    cudaMemsetAsync(gib,  0, B * G3 * sizeof(float));
    cudaMemsetAsync(ghb,  0, B * G3 * sizeof(float));
    cudaMemsetAsync(genb, 0, (size_t)B * V * sizeof(float));

    split_bf16<<<(TU * B * H + 255) / 256, 256>>>(u_enc, uAh, uAl, TU * B * H);
    split_bf16<<<(TZ * B * H + 255) / 256, 256>>>(z_enc, zAh, zAl, TZ * B * H);
    transpose_split<<<dim3(32, 32), 256>>>(Wa_u + (size_t)H * H, H, WuTh, WuTl);
    transpose_split<<<dim3(32, 32), 256>>>(Wa_z + (size_t)H * H, H, WzTh, WzTl);
    transpose_split<<<dim3(32, 32), 256>>>(W_c, H, WcTh, WcTl);

    small_gemm<true><<<dim3(16, 8), 128>>>(h, H, Wa_z, H, ba_z, hpz, H, 128);
    small_gemm<true><<<dim3(16, 8), 128>>>(h, H, Wa_u, H, ba_u, hpu, H, 128);

    energy_mma<128, 128, 4, 2><<<dim3(8, 32), 256>>>(uAh, uAl, WuTh, WuTl, hpu, v_u, su, TU);
    energy_mma< 32, 128, 1, 4><<<dim3(8, 16), 128>>>(zAh, zAl, WzTh, WzTl, hpz, v_z, sz, TZ);

    attn_ctx<<<dim3(B, 4), 256>>>(sz, z_enc, cz, TZ);
    attn_ctx<<<dim3(B, 4), 256>>>(su, u_enc, cu, TU);

    build_x<<<(B * XD + 255) / 256, 256>>>(cz, cu, emb, mt, xb);

    small_gemm<false><<<dim3(48, 5), 128>>>(xb, XD, W_ih, XD, b_ih, gib, G3, 512);
    small_gemm<false><<<dim3(48, 2), 128>>>(h,  H,  W_hh, H,  b_hh, ghb, G3, 512);

    gru_ln<<<B, 1024>>>(gib, ghb, h, ln_a, ln_b, out + (size_t)B * V, grub);

    small_gemm<true><<<dim3(16, 8), 128>>>(grub, H, W_c + (size_t)H * H, H, b_c, gpart, H, 128);
    energy_mma<32, 128, 1, 4><<<dim3(8, 16), 128>>>(zAh, zAl, WcTh, WcTl, gpart, W_v1, zcb, TZ);

    gen_gemm<<<dim3(V / 128, 4), 128>>>(grub, W_proj, b_proj, genb);

    softmax_stats<<<B, 256>>>(genb, zcb, b_v1, rsm, cpb);
    final_combine<<<dim3(V / 256, B), 256>>>(genb, pz, rsm, cpb, out);

    (void)in_sizes; (void)n_in; (void)out_size;
}

// round 5
// speedup vs baseline: 2.6930x; 1.0868x over previous
#include <cuda_runtime.h>
#include <cuda_bf16.h>
#include <math.h>

#define B   32
#define H   1024
#define TZ  16
#define TU  128
#define E   512
#define V   32000
#define XD  2560
#define G3  3072
#define LN_EPS 1e-3f

__device__ float d_hproj_z[B * H];
__device__ float d_hproj_u[B * H];
__device__ float d_gpart  [B * H];
__device__ float d_scores_z[B * TZ];
__device__ float d_scores_u[B * TU];
__device__ float d_zc      [B * TZ];
__device__ float d_ctx_z[B * H];
__device__ float d_ctx_u[B * H];
__device__ float d_x  [B * XD];
__device__ float d_gi [B * G3];
__device__ float d_gh [B * G3];
__device__ float d_gru[B * H];
__device__ float d_gen[B * V];
__device__ float d_rsum[B];
__device__ float d_cp[B * TZ];
__device__ __align__(16) __nv_bfloat16 d_uAh[TU * B * H];
__device__ __align__(16) __nv_bfloat16 d_uAl[TU * B * H];
__device__ __align__(16) __nv_bfloat16 d_zAh[TZ * B * H];
__device__ __align__(16) __nv_bfloat16 d_zAl[TZ * B * H];
__device__ __align__(16) __nv_bfloat16 d_WuTh[H * H];
__device__ __align__(16) __nv_bfloat16 d_WuTl[H * H];
__device__ __align__(16) __nv_bfloat16 d_WzTh[H * H];
__device__ __align__(16) __nv_bfloat16 d_WzTl[H * H];
__device__ __align__(16) __nv_bfloat16 d_WcTh[H * H];
__device__ __align__(16) __nv_bfloat16 d_WcTl[H * H];

__device__ __forceinline__ float fast_tanh(float x)
{
    float xc = fminf(fmaxf(x, -7.90531f), 7.90531f);
    float x2 = xc * xc;
    float p = fmaf(x2, -2.76076847742355e-16f, 2.00018790482477e-13f);
    p = fmaf(x2, p, -8.60467152213735e-11f);
    p = fmaf(x2, p,  5.12229709037114e-08f);
    p = fmaf(x2, p,  1.48572235717979e-05f);
    p = fmaf(x2, p,  6.37261928875436e-04f);
    p = fmaf(x2, p,  4.89352455891786e-03f);
    p = xc * p;
    float q = fmaf(x2, 1.19825839466702e-06f, 1.18534705686654e-04f);
    q = fmaf(x2, q, 2.26843463243900e-03f);
    q = fmaf(x2, q, 4.89352518554385e-03f);
    return __fdividef(p, q);
}

__global__ void split_bf16(const float* __restrict__ x,
                           __nv_bfloat16* __restrict__ hi,
                           __nv_bfloat16* __restrict__ lo, int n)
{
    int i = blockIdx.x * 256 + threadIdx.x;
    if (i >= n) return;
    float v = x[i];
    __nv_bfloat16 h = __float2bfloat16(v);
    hi[i] = h;
    lo[i] = __float2bfloat16(v - __bfloat162float(h));
}

__global__ void transpose_split(const float* __restrict__ W, int ldw,
                                __nv_bfloat16* __restrict__ Th,
                                __nv_bfloat16* __restrict__ Tl)
{
    __shared__ float tile[32][33];
    int k0 = blockIdx.x * 32, n0 = blockIdx.y * 32;
    int tx = threadIdx.x & 31, ty = threadIdx.x >> 5;
    for (int i = ty; i < 32; i += 8)
        tile[i][tx] = W[(size_t)(k0 + i) * ldw + n0 + tx];
    __syncthreads();
    for (int i = ty; i < 32; i += 8) {
        float v = tile[tx][i];
        __nv_bfloat16 h = __float2bfloat16(v);
        Th[(size_t)(n0 + i) * H + k0 + tx] = h;
        Tl[(size_t)(n0 + i) * H + k0 + tx] = __float2bfloat16(v - __bfloat162float(h));
    }
}

__device__ __forceinline__ void mma16816(float* c, const unsigned* a, const unsigned* b)
{
    asm volatile(
        "mma.sync.aligned.m16n8k16.row.col.f32.bf16.bf16.f32 "
        "{%0,%1,%2,%3}, {%4,%5,%6,%7}, {%8,%9}, {%0,%1,%2,%3};"
        : "+f"(c[0]), "+f"(c[1]), "+f"(c[2]), "+f"(c[3])
        : "r"(a[0]), "r"(a[1]), "r"(a[2]), "r"(a[3]), "r"(b[0]), "r"(b[1]));
}

__device__ __forceinline__ void cp16(void* s, const void* g)
{
    unsigned sa = (unsigned)__cvta_generic_to_shared(s);
    asm volatile("cp.async.cg.shared.global [%0], [%1], 16;\n" :: "r"(sa), "l"(g));
}
__device__ __forceinline__ void cp_commit() { asm volatile("cp.async.commit_group;\n"); }
template<int N> __device__ __forceinline__ void cp_wait() {
    asm volatile("cp.async.wait_group %0;\n" :: "n"(N));
}

// scores[b,t] += sum_n tanh((A@Wt^T)[r,n] + addv[b,n]) * v[n] ; r=t*B+b
// BM=64, BN=128, 8 warps (warp tile 32x32), double-buffered cp.async.
#define EBM 64
#define EBN 128
#define SKW 20
__global__ void __launch_bounds__(256, 2)
energy_mma(const __nv_bfloat16* __restrict__ Ah, const __nv_bfloat16* __restrict__ Al,
           const __nv_bfloat16* __restrict__ Wh, const __nv_bfloat16* __restrict__ Wl,
           const float* __restrict__ addv, const float* __restrict__ vvec,
           float* __restrict__ out, int T)
{
    __shared__ __align__(16) unsigned sAh[2][EBM * SKW], sAl[2][EBM * SKW];
    __shared__ __align__(16) unsigned sBh[2][EBN * SKW], sBl[2][EBN * SKW];
    int tid = threadIdx.x, wid = tid >> 5, lane = tid & 31;
    int wm = wid >> 2, wn = wid & 3;          // WM=2, WN=4
    int row0 = blockIdx.y * EBM, col0 = blockIdx.x * EBN;
    int l4 = lane >> 2, lm = lane & 3;

    float c[2][4][4];
#pragma unroll
    for (int mt = 0; mt < 2; mt++)
#pragma unroll
        for (int nt = 0; nt < 4; nt++)
#pragma unroll
            for (int e = 0; e < 4; e++) c[mt][nt][e] = 0.f;

    auto load_stage = [&](int st, int k0) {
#pragma unroll 1
        for (int i = tid; i < EBM * 4; i += 256) {
            int m = i >> 2, q = i & 3;
            size_t off = (size_t)(row0 + m) * H + k0 + q * 8;
            cp16(&sAh[st][m * SKW + q * 4], Ah + off);
            cp16(&sAl[st][m * SKW + q * 4], Al + off);
        }
#pragma unroll 1
        for (int i = tid; i < EBN * 4; i += 256) {
            int n = i >> 2, q = i & 3;
            size_t off = (size_t)(col0 + n) * H + k0 + q * 8;
            cp16(&sBh[st][n * SKW + q * 4], Wh + off);
            cp16(&sBl[st][n * SKW + q * 4], Wl + off);
        }
        cp_commit();
    };

    load_stage(0, 0);
    const int NC = H / 32;
    for (int kc = 0; kc < NC; kc++) {
        int p = kc & 1;
        if (kc + 1 < NC) { load_stage(p ^ 1, (kc + 1) * 32); cp_wait<1>(); }
        else             { cp_wait<0>(); }
        __syncthreads();
#pragma unroll
        for (int ks = 0; ks < 2; ks++) {
            int kw = ks * 8 + lm;
            unsigned ah[2][4], al[2][4];
#pragma unroll
            for (int mt = 0; mt < 2; mt++) {
                int r = wm * 32 + mt * 16 + l4;
                ah[mt][0] = sAh[p][r * SKW + kw];       ah[mt][1] = sAh[p][(r + 8) * SKW + kw];
                ah[mt][2] = sAh[p][r * SKW + kw + 4];   ah[mt][3] = sAh[p][(r + 8) * SKW + kw + 4];
                al[mt][0] = sAl[p][r * SKW + kw];       al[mt][1] = sAl[p][(r + 8) * SKW + kw];
                al[mt][2] = sAl[p][r * SKW + kw + 4];   al[mt][3] = sAl[p][(r + 8) * SKW + kw + 4];
            }
#pragma unroll
            for (int nt = 0; nt < 4; nt++) {
                int cn = wn * 32 + nt * 8 + l4;
                unsigned bh[2] = { sBh[p][cn * SKW + kw], sBh[p][cn * SKW + kw + 4] };
                unsigned bl[2] = { sBl[p][cn * SKW + kw], sBl[p][cn * SKW + kw + 4] };
#pragma unroll
                for (int mt = 0; mt < 2; mt++) {
                    mma16816(c[mt][nt], ah[mt], bh);
                    mma16816(c[mt][nt], ah[mt], bl);
                    mma16816(c[mt][nt], al[mt], bh);
                }
            }
        }
        __syncthreads();
    }
#pragma unroll
    for (int mt = 0; mt < 2; mt++)
#pragma unroll
        for (int half = 0; half < 2; half++) {
            int row = row0 + wm * 32 + mt * 16 + l4 + half * 8;
            int b = row & 31, t = row >> 5;
            float s = 0.f;
#pragma unroll
            for (int nt = 0; nt < 4; nt++) {
                int n0 = col0 + wn * 32 + nt * 8 + lm * 2;
                float e0 = fast_tanh(c[mt][nt][half * 2 + 0] + addv[b * H + n0]);
                float e1 = fast_tanh(c[mt][nt][half * 2 + 1] + addv[b * H + n0 + 1]);
                s = fmaf(e0, vvec[n0], s);
                s = fmaf(e1, vvec[n0 + 1], s);
            }
            s += __shfl_xor_sync(0xffffffff, s, 1);
            s += __shfl_xor_sync(0xffffffff, s, 2);
            if (lm == 0) atomicAdd(&out[b * T + t], s);
        }
}

// out[b][j] += sum_k x[b][k]*W(k,j) (+bias on y==0). KMAJOR: W[k*ldw+j], else W[j*ldw+k].
template<bool KMAJOR>
__global__ void __launch_bounds__(128)
small_gemm(const float* __restrict__ x, int ldx,
           const float* __restrict__ W, int ldw,
           const float* __restrict__ bias,
           float* __restrict__ out, int N, int kchunk)
{
    __shared__ float xs[32][33];
    __shared__ float Ws[32 * 65];
    int tid = threadIdx.x, tj = tid & 15, tb = tid >> 4;
    int j0 = blockIdx.x * 64;
    int kbeg = blockIdx.y * kchunk, kend = kbeg + kchunk;
    float acc[4][4] = {};
    for (int k0 = kbeg; k0 < kend; k0 += 32) {
        for (int i = tid; i < 256; i += 128) {
            int bb = i >> 3, q = i & 7;
            float4 vv = *(const float4*)&x[(size_t)bb * ldx + k0 + q * 4];
            xs[bb][q * 4 + 0] = vv.x; xs[bb][q * 4 + 1] = vv.y;
            xs[bb][q * 4 + 2] = vv.z; xs[bb][q * 4 + 3] = vv.w;
        }
        if (KMAJOR) {
            for (int i = tid; i < 512; i += 128) {
                int kk = i >> 4, jq = i & 15;
                float4 vv = *(const float4*)&W[(size_t)(k0 + kk) * ldw + j0 + jq * 4];
                Ws[kk * 65 + jq * 4 + 0] = vv.x; Ws[kk * 65 + jq * 4 + 1] = vv.y;
                Ws[kk * 65 + jq * 4 + 2] = vv.z; Ws[kk * 65 + jq * 4 + 3] = vv.w;
            }
        } else {
            for (int i = tid; i < 512; i += 128) {
                int j = i >> 3, q = i & 7;
                float4 vv = *(const float4*)&W[(size_t)(j0 + j) * ldw + k0 + q * 4];
                Ws[(q * 4 + 0) * 65 + j] = vv.x; Ws[(q * 4 + 1) * 65 + j] = vv.y;
                Ws[(q * 4 + 2) * 65 + j] = vv.z; Ws[(q * 4 + 3) * 65 + j] = vv.w;
            }
        }
        __syncthreads();
#pragma unroll 8
        for (int kk = 0; kk < 32; kk++) {
            float a[4], w[4];
#pragma unroll
            for (int i = 0; i < 4; i++) a[i] = xs[tb * 4 + i][kk];
#pragma unroll
            for (int j = 0; j < 4; j++) w[j] = Ws[kk * 65 + tj * 4 + j];
#pragma unroll
            for (int i = 0; i < 4; i++)
#pragma unroll
                for (int j = 0; j < 4; j++) acc[i][j] = fmaf(a[i], w[j], acc[i][j]);
        }
        __syncthreads();
    }
#pragma unroll
    for (int i = 0; i < 4; i++)
#pragma unroll
        for (int j = 0; j < 4; j++) {
            int jj = j0 + tj * 4 + j;
            float v = acc[i][j] + ((blockIdx.y == 0) ? bias[jj] : 0.f);
            atomicAdd(&out[(tb * 4 + i) * N + jj], v);
        }
}

__global__ void attn_ctx(const float* __restrict__ scores,
                         const float* __restrict__ enc,
                         float* __restrict__ ctx, int T)
{
    int b = blockIdx.x, tid = threadIdx.x;
    __shared__ float w[TU];
    __shared__ float inv_s;
    if (tid < 32) {
        float m = -1e30f;
        for (int t = tid; t < T; t += 32) m = fmaxf(m, scores[b * T + t]);
#pragma unroll
        for (int o = 16; o > 0; o >>= 1) m = fmaxf(m, __shfl_xor_sync(0xffffffff, m, o));
        float s = 0.f;
        for (int t = tid; t < T; t += 32) {
            float e = __expf(scores[b * T + t] - m);
            w[t] = e; s += e;
        }
#pragma unroll
        for (int o = 16; o > 0; o >>= 1) s += __shfl_xor_sync(0xffffffff, s, o);
        if (tid == 0) inv_s = 1.f / s;
    }
    __syncthreads();
    int j = blockIdx.y * 256 + tid;
    float acc = 0.f;
    for (int t = 0; t < T; t++) acc = fmaf(w[t], enc[(size_t)(t * B + b) * H + j], acc);
    ctx[b * H + j] = acc * inv_s;
}

__global__ void build_x(const float* __restrict__ cz, const float* __restrict__ cu,
                        const float* __restrict__ emb, const int* __restrict__ mt,
                        float* __restrict__ x)
{
    int idx = blockIdx.x * 256 + threadIdx.x;
    if (idx >= B * XD) return;
    int b = idx / XD, k = idx % XD;
    float vl;
    if (k < H)           vl = cz[b * H + k];
    else if (k < 2 * H)  vl = cu[b * H + (k - H)];
    else                 vl = emb[(size_t)mt[b] * E + (k - 2 * H)];
    x[idx] = vl;
}

__global__ void gru_ln(const float* __restrict__ gi, const float* __restrict__ gh,
                       const float* __restrict__ h,
                       const float* __restrict__ lna, const float* __restrict__ lnb,
                       float* __restrict__ hnew_out, float* __restrict__ gru_out)
{
    int b = blockIdx.x, j = threadIdx.x;
    float ir = gi[b * G3 + j], iz = gi[b * G3 + H + j], inn = gi[b * G3 + 2 * H + j];
    float hr = gh[b * G3 + j], hz = gh[b * G3 + H + j], hn  = gh[b * G3 + 2 * H + j];
    float r  = 1.f / (1.f + __expf(-(ir + hr)));
    float zg = 1.f / (1.f + __expf(-(iz + hz)));
    float n  = fast_tanh(inn + r * hn);
    float hv = h[b * H + j];
    float hnew = (1.f - zg) * n + zg * hv;
    hnew_out[b * H + j] = hnew;
    __shared__ float sh[1024];
    sh[j] = hnew; __syncthreads();
    for (int s = 512; s > 0; s >>= 1) { if (j < s) sh[j] += sh[j + s]; __syncthreads(); }
    float mu = sh[0] * (1.f / H); __syncthreads();
    float d = hnew - mu;
    sh[j] = d * d; __syncthreads();
    for (int s = 512; s > 0; s >>= 1) { if (j < s) sh[j] += sh[j + s]; __syncthreads(); }
    float sigma = sqrtf(sh[0] / (float)(H - 1));
    gru_out[b * H + j] = d / (sigma + LN_EPS) * lna[j] + lnb[j];
}

__global__ void __launch_bounds__(128)
gen_gemm(const float* __restrict__ g, const float* __restrict__ Wp,
         const float* __restrict__ bproj, float* __restrict__ gen)
{
    __shared__ float gs[32][65];
    int tid = threadIdx.x, tv = tid & 31, tb = tid >> 5;
    int v0 = blockIdx.x * 128 + tv * 4;
    int b0 = tb * 8;
    int kbeg = blockIdx.y * 256;
    float acc[8][4] = {};
    for (int kb = 0; kb < 256; kb += 64) {
        for (int i = tid; i < 512; i += 128) {
            int bb = i >> 4, q = i & 15;
            float4 vv = *(const float4*)&g[(size_t)bb * H + kbeg + kb + q * 4];
            gs[bb][q * 4 + 0] = vv.x; gs[bb][q * 4 + 1] = vv.y;
            gs[bb][q * 4 + 2] = vv.z; gs[bb][q * 4 + 3] = vv.w;
        }
        __syncthreads();
#pragma unroll 4
        for (int kk = 0; kk < 64; kk++) {
            float4 w = *(const float4*)&Wp[(size_t)(kbeg + kb + kk) * V + v0];
            float a[8];
#pragma unroll
            for (int i = 0; i < 8; i++) a[i] = gs[b0 + i][kk];
#pragma unroll
            for (int i = 0; i < 8; i++) {
                acc[i][0] = fmaf(a[i], w.x, acc[i][0]);
                acc[i][1] = fmaf(a[i], w.y, acc[i][1]);
                acc[i][2] = fmaf(a[i], w.z, acc[i][2]);
                acc[i][3] = fmaf(a[i], w.w, acc[i][3]);
            }
        }
        __syncthreads();
    }
#pragma unroll
    for (int i = 0; i < 8; i++)
#pragma unroll
        for (int j = 0; j < 4; j++) {
            float v = acc[i][j] + ((blockIdx.y == 0) ? bproj[v0 + j] : 0.f);
            atomicAdd(&gen[(size_t)(b0 + i) * V + v0 + j], v);
        }
}

__global__ void softmax_stats(float* __restrict__ gen,
                              const float* __restrict__ zc, const float* __restrict__ bv1,
                              float* __restrict__ rsum_inv, float* __restrict__ cp)
{
    int b = blockIdx.x, tid = threadIdx.x;
    float bz = bv1[0];
    float mx = -1e30f;
    for (int v = tid; v < V; v += 256) mx = fmaxf(mx, gen[(size_t)b * V + v]);
    if (tid < TZ) mx = fmaxf(mx, zc[b * TZ + tid] + bz);
    __shared__ float sh[256];
    sh[tid] = mx; __syncthreads();
    for (int s = 128; s > 0; s >>= 1) { if (tid < s) sh[tid] = fmaxf(sh[tid], sh[tid + s]); __syncthreads(); }
    mx = sh[0]; __syncthreads();
    float s = 0.f;
    for (int v = tid; v < V; v += 256) {
        float e = __expf(gen[(size_t)b * V + v] - mx);
        gen[(size_t)b * V + v] = e;
        s += e;
    }
    if (tid < TZ) s += __expf(zc[b * TZ + tid] + bz - mx);
    sh[tid] = s; __syncthreads();
    for (int st = 128; st > 0; st >>= 1) { if (tid < st) sh[tid] += sh[tid + st]; __syncthreads(); }
    s = sh[0];
    if (tid == 0) rsum_inv[b] = 1.f / s;
    if (tid < TZ) cp[b * TZ + tid] = __expf(zc[b * TZ + tid] + bz - mx) / s;
}

__global__ void final_combine(const float* __restrict__ gen,
                              const float* __restrict__ pz,
                              const float* __restrict__ rsum_inv,
                              const float* __restrict__ cp,
                              float* __restrict__ out)
{
    int b = blockIdx.y;
    int v = blockIdx.x * 256 + threadIdx.x;
    __shared__ float cps[TZ];
    __shared__ float inv_s;
    if (threadIdx.x < TZ) cps[threadIdx.x] = cp[b * TZ + threadIdx.x];
    if (threadIdx.x == 0) inv_s = rsum_inv[b];
    __syncthreads();
    float gp = gen[(size_t)b * V + v] * inv_s;
    float acc = 0.f;
#pragma unroll
    for (int t = 0; t < TZ; t++) acc = fmaf(cps[t], pz[(size_t)(t * B + b) * V + v], acc);
    out[(size_t)b * V + v] = gp + (v >= 4 ? acc : 0.f);
}

extern "C" void kernel_launch(void* const* d_in, const int* in_sizes, int n_in,
                              void* d_out, int out_size)
{
    const float* z_enc  = (const float*)d_in[0];
    const float* pz     = (const float*)d_in[1];
    const float* u_enc  = (const float*)d_in[2];
    const int*   mt     = (const int*)  d_in[3];
    const float* h      = (const float*)d_in[4];
    const float* emb    = (const float*)d_in[5];
    const float* Wa_z   = (const float*)d_in[6];
    const float* ba_z   = (const float*)d_in[7];
    const float* v_z    = (const float*)d_in[8];
    const float* Wa_u   = (const float*)d_in[9];
    const float* ba_u   = (const float*)d_in[10];
    const float* v_u    = (const float*)d_in[11];
    const float* W_ih   = (const float*)d_in[12];
    const float* W_hh   = (const float*)d_in[13];
    const float* b_ih   = (const float*)d_in[14];
    const float* b_hh   = (const float*)d_in[15];
    const float* ln_a   = (const float*)d_in[16];
    const float* ln_b   = (const float*)d_in[17];
    const float* W_proj = (const float*)d_in[18];
    const float* b_proj = (const float*)d_in[19];
    const float* W_c    = (const float*)d_in[20];
    const float* b_c    = (const float*)d_in[21];
    const float* W_v1   = (const float*)d_in[22];
    const float* b_v1   = (const float*)d_in[23];
    float* out = (float*)d_out;

    float *hpz, *hpu, *gpart, *sz, *su, *zcb, *cz, *cu, *xb, *gib, *ghb, *grub, *genb, *rsm, *cpb;
    __nv_bfloat16 *uAh, *uAl, *zAh, *zAl, *WuTh, *WuTl, *WzTh, *WzTl, *WcTh, *WcTl;
    cudaGetSymbolAddress((void**)&hpz,  d_hproj_z);
    cudaGetSymbolAddress((void**)&hpu,  d_hproj_u);
    cudaGetSymbolAddress((void**)&gpart,d_gpart);
    cudaGetSymbolAddress((void**)&sz,   d_scores_z);
    cudaGetSymbolAddress((void**)&su,   d_scores_u);
    cudaGetSymbolAddress((void**)&zcb,  d_zc);
    cudaGetSymbolAddress((void**)&cz,   d_ctx_z);
    cudaGetSymbolAddress((void**)&cu,   d_ctx_u);
    cudaGetSymbolAddress((void**)&xb,   d_x);
    cudaGetSymbolAddress((void**)&gib,  d_gi);
    cudaGetSymbolAddress((void**)&ghb,  d_gh);
    cudaGetSymbolAddress((void**)&grub, d_gru);
    cudaGetSymbolAddress((void**)&genb, d_gen);
    cudaGetSymbolAddress((void**)&rsm,  d_rsum);
    cudaGetSymbolAddress((void**)&cpb,  d_cp);
    cudaGetSymbolAddress((void**)&uAh,  d_uAh);
    cudaGetSymbolAddress((void**)&uAl,  d_uAl);
    cudaGetSymbolAddress((void**)&zAh,  d_zAh);
    cudaGetSymbolAddress((void**)&zAl,  d_zAl);
    cudaGetSymbolAddress((void**)&WuTh, d_WuTh);
    cudaGetSymbolAddress((void**)&WuTl, d_WuTl);
    cudaGetSymbolAddress((void**)&WzTh, d_WzTh);
    cudaGetSymbolAddress((void**)&WzTl, d_WzTl);
    cudaGetSymbolAddress((void**)&WcTh, d_WcTh);
    cudaGetSymbolAddress((void**)&WcTl, d_WcTl);

    cudaMemsetAsync(hpz,  0, B * H  * sizeof(float));
    cudaMemsetAsync(hpu,  0, B * H  * sizeof(float));
    cudaMemsetAsync(gpart,0, B * H  * sizeof(float));
    cudaMemsetAsync(sz,   0, B * TZ * sizeof(float));
    cudaMemsetAsync(su,   0, B * TU * sizeof(float));
    cudaMemsetAsync(zcb,  0, B * TZ * sizeof(float));
    cudaMemsetAsync(gib,  0, B * G3 * sizeof(float));
    cudaMemsetAsync(ghb,  0, B * G3 * sizeof(float));
    cudaMemsetAsync(genb, 0, (size_t)B * V * sizeof(float));

    split_bf16<<<(TU * B * H + 255) / 256, 256>>>(u_enc, uAh, uAl, TU * B * H);
    split_bf16<<<(TZ * B * H + 255) / 256, 256>>>(z_enc, zAh, zAl, TZ * B * H);
    transpose_split<<<dim3(32, 32), 256>>>(Wa_u + (size_t)H * H, H, WuTh, WuTl);
    transpose_split<<<dim3(32, 32), 256>>>(Wa_z + (size_t)H * H, H, WzTh, WzTl);
    transpose_split<<<dim3(32, 32), 256>>>(W_c, H, WcTh, WcTl);

    small_gemm<true><<<dim3(16, 8), 128>>>(h, H, Wa_z, H, ba_z, hpz, H, 128);
    small_gemm<true><<<dim3(16, 8), 128>>>(h, H, Wa_u, H, ba_u, hpu, H, 128);

    energy_mma<<<dim3(8, (TU * B) / EBM), 256>>>(uAh, uAl, WuTh, WuTl, hpu, v_u, su, TU);
    energy_mma<<<dim3(8, (TZ * B) / EBM), 256>>>(zAh, zAl, WzTh, WzTl, hpz, v_z, sz, TZ);

    attn_ctx<<<dim3(B, 4), 256>>>(sz, z_enc, cz, TZ);
    attn_ctx<<<dim3(B, 4), 256>>>(su, u_enc, cu, TU);

    build_x<<<(B * XD + 255) / 256, 256>>>(cz, cu, emb, mt, xb);

    small_gemm<false><<<dim3(48, 5), 128>>>(xb, XD, W_ih, XD, b_ih, gib, G3, 512);
    small_gemm<false><<<dim3(48, 2), 128>>>(h,  H,  W_hh, H,  b_hh, ghb, G3, 512);

    gru_ln<<<B, 1024>>>(gib, ghb, h, ln_a, ln_b, out + (size_t)B * V, grub);

    small_gemm<true><<<dim3(16, 8), 128>>>(grub, H, W_c + (size_t)H * H, H, b_c, gpart, H, 128);
    energy_mma<<<dim3(8, (TZ * B) / EBM), 256>>>(zAh, zAl, WcTh, WcTl, gpart, W_v1, zcb, TZ);

    gen_gemm<<<dim3(V / 128, 4), 128>>>(grub, W_proj, b_proj, genb);

    softmax_stats<<<B, 256>>>(genb, zcb, b_v1, rsm, cpb);
    final_combine<<<dim3(V / 256, B), 256>>>(genb, pz, rsm, cpb, out);

    (void)in_sizes; (void)n_in; (void)out_size;
}

// round 6
// speedup vs baseline: 2.8020x; 1.0405x over previous
#include <cuda_runtime.h>
#include <cuda_bf16.h>
#include <math.h>

#define B   32
#define H   1024
#define TZ  16
#define TU  128
#define E   512
#define V   32000
#define XD  2560
#define G3  3072
#define LN_EPS 1e-3f

__device__ float d_hproj_z[B * H];
__device__ float d_hproj_u[B * H];
__device__ float d_gpart  [B * H];
__device__ float d_scores_z[B * TZ];
__device__ float d_scores_u[B * TU];
__device__ float d_zc      [B * TZ];
__device__ float d_ctx_z[B * H];
__device__ float d_ctx_u[B * H];
__device__ float d_x  [B * XD];
__device__ float d_gi [B * G3];
__device__ float d_gh [B * G3];
__device__ float d_gru[B * H];
__device__ float d_gen[B * V];
__device__ float d_rsum[B];
__device__ float d_cp[B * TZ];
__device__ __align__(16) __nv_bfloat16 d_uAh[TU * B * H];
__device__ __align__(16) __nv_bfloat16 d_uAl[TU * B * H];
__device__ __align__(16) __nv_bfloat16 d_zAh[TZ * B * H];
__device__ __align__(16) __nv_bfloat16 d_zAl[TZ * B * H];
__device__ __align__(16) __nv_bfloat16 d_WuTh[H * H];
__device__ __align__(16) __nv_bfloat16 d_WuTl[H * H];
__device__ __align__(16) __nv_bfloat16 d_WzTh[H * H];
__device__ __align__(16) __nv_bfloat16 d_WzTl[H * H];
__device__ __align__(16) __nv_bfloat16 d_WcTh[H * H];
__device__ __align__(16) __nv_bfloat16 d_WcTl[H * H];

__device__ __forceinline__ float fast_tanh(float x)
{
    float xc = fminf(fmaxf(x, -7.90531f), 7.90531f);
    float x2 = xc * xc;
    float p = fmaf(x2, -2.76076847742355e-16f, 2.00018790482477e-13f);
    p = fmaf(x2, p, -8.60467152213735e-11f);
    p = fmaf(x2, p,  5.12229709037114e-08f);
    p = fmaf(x2, p,  1.48572235717979e-05f);
    p = fmaf(x2, p,  6.37261928875436e-04f);
    p = fmaf(x2, p,  4.89352455891786e-03f);
    p = xc * p;
    float q = fmaf(x2, 1.19825839466702e-06f, 1.18534705686654e-04f);
    q = fmaf(x2, q, 2.26843463243900e-03f);
    q = fmaf(x2, q, 4.89352518554385e-03f);
    return __fdividef(p, q);
}

__global__ void zero_all(float* hpz, float* hpu, float* gpart, float* sz, float* su,
                         float* zcb, float* gi, float* gh, float* gen)
{
    int i = blockIdx.x * 256 + threadIdx.x;
    if (i < B * H)  { hpz[i] = 0.f; hpu[i] = 0.f; gpart[i] = 0.f; }
    if (i < B * TZ) { sz[i] = 0.f; zcb[i] = 0.f; }
    if (i < B * TU) su[i] = 0.f;
    if (i < B * G3) { gi[i] = 0.f; gh[i] = 0.f; }
    if (i < B * V)  gen[i] = 0.f;
}

__global__ void split_bf16(const float* __restrict__ x,
                           __nv_bfloat16* __restrict__ hi,
                           __nv_bfloat16* __restrict__ lo, int n)
{
    int i = blockIdx.x * 256 + threadIdx.x;
    if (i >= n) return;
    float v = x[i];
    __nv_bfloat16 h = __float2bfloat16(v);
    hi[i] = h;
    lo[i] = __float2bfloat16(v - __bfloat162float(h));
}

__global__ void transpose_split(const float* __restrict__ W, int ldw,
                                __nv_bfloat16* __restrict__ Th,
                                __nv_bfloat16* __restrict__ Tl)
{
    __shared__ float tile[32][33];
    int k0 = blockIdx.x * 32, n0 = blockIdx.y * 32;
    int tx = threadIdx.x & 31, ty = threadIdx.x >> 5;
    for (int i = ty; i < 32; i += 8)
        tile[i][tx] = W[(size_t)(k0 + i) * ldw + n0 + tx];
    __syncthreads();
    for (int i = ty; i < 32; i += 8) {
        float v = tile[tx][i];
        __nv_bfloat16 h = __float2bfloat16(v);
        Th[(size_t)(n0 + i) * H + k0 + tx] = h;
        Tl[(size_t)(n0 + i) * H + k0 + tx] = __float2bfloat16(v - __bfloat162float(h));
    }
}

__device__ __forceinline__ void mma16816(float* c, const unsigned* a, const unsigned* b)
{
    asm volatile(
        "mma.sync.aligned.m16n8k16.row.col.f32.bf16.bf16.f32 "
        "{%0,%1,%2,%3}, {%4,%5,%6,%7}, {%8,%9}, {%0,%1,%2,%3};"
        : "+f"(c[0]), "+f"(c[1]), "+f"(c[2]), "+f"(c[3])
        : "r"(a[0]), "r"(a[1]), "r"(a[2]), "r"(a[3]), "r"(b[0]), "r"(b[1]));
}

__device__ __forceinline__ void ldsm_x4(unsigned* r, const void* p)
{
    unsigned a = (unsigned)__cvta_generic_to_shared(p);
    asm volatile("ldmatrix.sync.aligned.m8n8.x4.shared.b16 {%0,%1,%2,%3}, [%4];"
        : "=r"(r[0]), "=r"(r[1]), "=r"(r[2]), "=r"(r[3]) : "r"(a));
}

__device__ __forceinline__ void cp16(void* s, const void* g)
{
    unsigned sa = (unsigned)__cvta_generic_to_shared(s);
    asm volatile("cp.async.cg.shared.global [%0], [%1], 16;\n" :: "r"(sa), "l"(g));
}
__device__ __forceinline__ void cp_commit() { asm volatile("cp.async.commit_group;\n"); }
template<int N> __device__ __forceinline__ void cp_wait() {
    asm volatile("cp.async.wait_group %0;\n" :: "n"(N));
}

// scores[b,t] += sum_n tanh((A@Wt^T)[r,n] + addv[b,n]) * v[n] ; r=t*B+b
// BM=64, BN=128, 8 warps (warp tile 32x32), double-buffered cp.async, ldmatrix loads.
#define EBM 64
#define EBN 128
#define SKW 20
__global__ void __launch_bounds__(256, 2)
energy_mma(const __nv_bfloat16* __restrict__ Ah, const __nv_bfloat16* __restrict__ Al,
           const __nv_bfloat16* __restrict__ Wh, const __nv_bfloat16* __restrict__ Wl,
           const float* __restrict__ addv, const float* __restrict__ vvec,
           float* __restrict__ out, int T)
{
    __shared__ __align__(16) unsigned sAh[2][EBM * SKW], sAl[2][EBM * SKW];
    __shared__ __align__(16) unsigned sBh[2][EBN * SKW], sBl[2][EBN * SKW];
    int tid = threadIdx.x, wid = tid >> 5, lane = tid & 31;
    int wm = wid >> 2, wn = wid & 3;          // WM=2, WN=4
    int row0 = blockIdx.y * EBM, col0 = blockIdx.x * EBN;
    int l4 = lane >> 2, lm = lane & 3, lane7 = lane & 7;

    // ldmatrix lane base indices (in unsigned words)
    int idxA = (wm * 32 + lane7 + ((lane >> 3) & 1) * 8) * SKW + ((lane >> 4) & 1) * 4;
    int idxB = (wn * 32 + lane7 + ((lane >> 4) & 1) * 8) * SKW + ((lane >> 3) & 1) * 4;

    float c[2][4][4];
#pragma unroll
    for (int mt = 0; mt < 2; mt++)
#pragma unroll
        for (int nt = 0; nt < 4; nt++)
#pragma unroll
            for (int e = 0; e < 4; e++) c[mt][nt][e] = 0.f;

    auto load_stage = [&](int st, int k0) {
#pragma unroll 1
        for (int i = tid; i < EBM * 4; i += 256) {
            int m = i >> 2, q = i & 3;
            size_t off = (size_t)(row0 + m) * H + k0 + q * 8;
            cp16(&sAh[st][m * SKW + q * 4], Ah + off);
            cp16(&sAl[st][m * SKW + q * 4], Al + off);
        }
#pragma unroll 1
        for (int i = tid; i < EBN * 4; i += 256) {
            int n = i >> 2, q = i & 3;
            size_t off = (size_t)(col0 + n) * H + k0 + q * 8;
            cp16(&sBh[st][n * SKW + q * 4], Wh + off);
            cp16(&sBl[st][n * SKW + q * 4], Wl + off);
        }
        cp_commit();
    };

    load_stage(0, 0);
    const int NC = H / 32;
    for (int kc = 0; kc < NC; kc++) {
        int p = kc & 1;
        if (kc + 1 < NC) { load_stage(p ^ 1, (kc + 1) * 32); cp_wait<1>(); }
        else             { cp_wait<0>(); }
        __syncthreads();
#pragma unroll
        for (int ks = 0; ks < 2; ks++) {
            int ko = ks * 8;
            unsigned ah[2][4], al[2][4], bh2[2][4], bl2[2][4];
            ldsm_x4(ah[0],  &sAh[p][idxA + ko]);
            ldsm_x4(ah[1],  &sAh[p][idxA + 16 * SKW + ko]);
            ldsm_x4(al[0],  &sAl[p][idxA + ko]);
            ldsm_x4(al[1],  &sAl[p][idxA + 16 * SKW + ko]);
            ldsm_x4(bh2[0], &sBh[p][idxB + ko]);
            ldsm_x4(bh2[1], &sBh[p][idxB + 16 * SKW + ko]);
            ldsm_x4(bl2[0], &sBl[p][idxB + ko]);
            ldsm_x4(bl2[1], &sBl[p][idxB + 16 * SKW + ko]);
#pragma unroll
            for (int nt = 0; nt < 4; nt++) {
                const unsigned* bh = &bh2[nt >> 1][(nt & 1) * 2];
                const unsigned* bl = &bl2[nt >> 1][(nt & 1) * 2];
#pragma unroll
                for (int mt = 0; mt < 2; mt++) {
                    mma16816(c[mt][nt], ah[mt], bh);
                    mma16816(c[mt][nt], ah[mt], bl);
                    mma16816(c[mt][nt], al[mt], bh);
                }
            }
        }
        __syncthreads();
    }
#pragma unroll
    for (int mt = 0; mt < 2; mt++)
#pragma unroll
        for (int half = 0; half < 2; half++) {
            int row = row0 + wm * 32 + mt * 16 + l4 + half * 8;
            int b = row & 31, t = row >> 5;
            float s = 0.f;
#pragma unroll
            for (int nt = 0; nt < 4; nt++) {
                int n0 = col0 + wn * 32 + nt * 8 + lm * 2;
                float e0 = fast_tanh(c[mt][nt][half * 2 + 0] + addv[b * H + n0]);
                float e1 = fast_tanh(c[mt][nt][half * 2 + 1] + addv[b * H + n0 + 1]);
                s = fmaf(e0, vvec[n0], s);
                s = fmaf(e1, vvec[n0 + 1], s);
            }
            s += __shfl_xor_sync(0xffffffff, s, 1);
            s += __shfl_xor_sync(0xffffffff, s, 2);
            if (lm == 0) atomicAdd(&out[b * T + t], s);
        }
}

// out[b][j] += sum_k x[b][k]*W(k,j) (+bias on y==0). KMAJOR: W[k*ldw+j], else W[j*ldw+k].
template<bool KMAJOR>
__global__ void __launch_bounds__(128)
small_gemm(const float* __restrict__ x, int ldx,
           const float* __restrict__ W, int ldw,
           const float* __restrict__ bias,
           float* __restrict__ out, int N, int kchunk)
{
    __shared__ float xs[32][33];
    __shared__ float Ws[32 * 65];
    int tid = threadIdx.x, tj = tid & 15, tb = tid >> 4;
    int j0 = blockIdx.x * 64;
    int kbeg = blockIdx.y * kchunk, kend = kbeg + kchunk;
    float acc[4][4] = {};
    for (int k0 = kbeg; k0 < kend; k0 += 32) {
        for (int i = tid; i < 256; i += 128) {
            int bb = i >> 3, q = i & 7;
            float4 vv = *(const float4*)&x[(size_t)bb * ldx + k0 + q * 4];
            xs[bb][q * 4 + 0] = vv.x; xs[bb][q * 4 + 1] = vv.y;
            xs[bb][q * 4 + 2] = vv.z; xs[bb][q * 4 + 3] = vv.w;
        }
        if (KMAJOR) {
            for (int i = tid; i < 512; i += 128) {
                int kk = i >> 4, jq = i & 15;
                float4 vv = *(const float4*)&W[(size_t)(k0 + kk) * ldw + j0 + jq * 4];
                Ws[kk * 65 + jq * 4 + 0] = vv.x; Ws[kk * 65 + jq * 4 + 1] = vv.y;
                Ws[kk * 65 + jq * 4 + 2] = vv.z; Ws[kk * 65 + jq * 4 + 3] = vv.w;
            }
        } else {
            for (int i = tid; i < 512; i += 128) {
                int j = i >> 3, q = i & 7;
                float4 vv = *(const float4*)&W[(size_t)(j0 + j) * ldw + k0 + q * 4];
                Ws[(q * 4 + 0) * 65 + j] = vv.x; Ws[(q * 4 + 1) * 65 + j] = vv.y;
                Ws[(q * 4 + 2) * 65 + j] = vv.z; Ws[(q * 4 + 3) * 65 + j] = vv.w;
            }
        }
        __syncthreads();
#pragma unroll 8
        for (int kk = 0; kk < 32; kk++) {
            float a[4], w[4];
#pragma unroll
            for (int i = 0; i < 4; i++) a[i] = xs[tb * 4 + i][kk];
#pragma unroll
            for (int j = 0; j < 4; j++) w[j] = Ws[kk * 65 + tj * 4 + j];
#pragma unroll
            for (int i = 0; i < 4; i++)
#pragma unroll
                for (int j = 0; j < 4; j++) acc[i][j] = fmaf(a[i], w[j], acc[i][j]);
        }
        __syncthreads();
    }
#pragma unroll
    for (int i = 0; i < 4; i++)
#pragma unroll
        for (int j = 0; j < 4; j++) {
            int jj = j0 + tj * 4 + j;
            float v = acc[i][j] + ((blockIdx.y == 0) ? bias[jj] : 0.f);
            atomicAdd(&out[(tb * 4 + i) * N + jj], v);
        }
}

__global__ void attn_ctx(const float* __restrict__ scores,
                         const float* __restrict__ enc,
                         float* __restrict__ ctx, int T)
{
    int b = blockIdx.x, tid = threadIdx.x;
    __shared__ float w[TU];
    __shared__ float inv_s;
    if (tid < 32) {
        float m = -1e30f;
        for (int t = tid; t < T; t += 32) m = fmaxf(m, scores[b * T + t]);
#pragma unroll
        for (int o = 16; o > 0; o >>= 1) m = fmaxf(m, __shfl_xor_sync(0xffffffff, m, o));
        float s = 0.f;
        for (int t = tid; t < T; t += 32) {
            float e = __expf(scores[b * T + t] - m);
            w[t] = e; s += e;
        }
#pragma unroll
        for (int o = 16; o > 0; o >>= 1) s += __shfl_xor_sync(0xffffffff, s, o);
        if (tid == 0) inv_s = 1.f / s;
    }
    __syncthreads();
    int j = blockIdx.y * 256 + tid;
    float acc = 0.f;
    for (int t = 0; t < T; t++) acc = fmaf(w[t], enc[(size_t)(t * B + b) * H + j], acc);
    ctx[b * H + j] = acc * inv_s;
}

__global__ void build_x(const float* __restrict__ cz, const float* __restrict__ cu,
                        const float* __restrict__ emb, const int* __restrict__ mt,
                        float* __restrict__ x)
{
    int idx = blockIdx.x * 256 + threadIdx.x;
    if (idx >= B * XD) return;
    int b = idx / XD, k = idx % XD;
    float vl;
    if (k < H)           vl = cz[b * H + k];
    else if (k < 2 * H)  vl = cu[b * H + (k - H)];
    else                 vl = emb[(size_t)mt[b] * E + (k - 2 * H)];
    x[idx] = vl;
}

__global__ void gru_ln(const float* __restrict__ gi, const float* __restrict__ gh,
                       const float* __restrict__ h,
                       const float* __restrict__ lna, const float* __restrict__ lnb,
                       float* __restrict__ hnew_out, float* __restrict__ gru_out)
{
    int b = blockIdx.x, j = threadIdx.x;
    float ir = gi[b * G3 + j], iz = gi[b * G3 + H + j], inn = gi[b * G3 + 2 * H + j];
    float hr = gh[b * G3 + j], hz = gh[b * G3 + H + j], hn  = gh[b * G3 + 2 * H + j];
    float r  = 1.f / (1.f + __expf(-(ir + hr)));
    float zg = 1.f / (1.f + __expf(-(iz + hz)));
    float n  = fast_tanh(inn + r * hn);
    float hv = h[b * H + j];
    float hnew = (1.f - zg) * n + zg * hv;
    hnew_out[b * H + j] = hnew;
    __shared__ float sh[1024];
    sh[j] = hnew; __syncthreads();
    for (int s = 512; s > 0; s >>= 1) { if (j < s) sh[j] += sh[j + s]; __syncthreads(); }
    float mu = sh[0] * (1.f / H); __syncthreads();
    float d = hnew - mu;
    sh[j] = d * d; __syncthreads();
    for (int s = 512; s > 0; s >>= 1) { if (j < s) sh[j] += sh[j + s]; __syncthreads(); }
    float sigma = sqrtf(sh[0] / (float)(H - 1));
    gru_out[b * H + j] = d / (sigma + LN_EPS) * lna[j] + lnb[j];
}

__global__ void __launch_bounds__(128)
gen_gemm(const float* __restrict__ g, const float* __restrict__ Wp,
         const float* __restrict__ bproj, float* __restrict__ gen)
{
    __shared__ float gs[32][65];
    int tid = threadIdx.x, tv = tid & 31, tb = tid >> 5;
    int v0 = blockIdx.x * 128 + tv * 4;
    int b0 = tb * 8;
    int kbeg = blockIdx.y * 256;
    float acc[8][4] = {};
    for (int kb = 0; kb < 256; kb += 64) {
        for (int i = tid; i < 512; i += 128) {
            int bb = i >> 4, q = i & 15;
            float4 vv = *(const float4*)&g[(size_t)bb * H + kbeg + kb + q * 4];
            gs[bb][q * 4 + 0] = vv.x; gs[bb][q * 4 + 1] = vv.y;
            gs[bb][q * 4 + 2] = vv.z; gs[bb][q * 4 + 3] = vv.w;
        }
        __syncthreads();
#pragma unroll 4
        for (int kk = 0; kk < 64; kk++) {
            float4 w = *(const float4*)&Wp[(size_t)(kbeg + kb + kk) * V + v0];
            float a[8];
#pragma unroll
            for (int i = 0; i < 8; i++) a[i] = gs[b0 + i][kk];
#pragma unroll
            for (int i = 0; i < 8; i++) {
                acc[i][0] = fmaf(a[i], w.x, acc[i][0]);
                acc[i][1] = fmaf(a[i], w.y, acc[i][1]);
                acc[i][2] = fmaf(a[i], w.z, acc[i][2]);
                acc[i][3] = fmaf(a[i], w.w, acc[i][3]);
            }
        }
        __syncthreads();
    }
#pragma unroll
    for (int i = 0; i < 8; i++)
#pragma unroll
        for (int j = 0; j < 4; j++) {
            float v = acc[i][j] + ((blockIdx.y == 0) ? bproj[v0 + j] : 0.f);
            atomicAdd(&gen[(size_t)(b0 + i) * V + v0 + j], v);
        }
}

__global__ void softmax_stats(float* __restrict__ gen,
                              const float* __restrict__ zc, const float* __restrict__ bv1,
                              float* __restrict__ rsum_inv, float* __restrict__ cp)
{
    int b = blockIdx.x, tid = threadIdx.x;
    float bz = bv1[0];
    float mx = -1e30f;
    for (int v = tid; v < V; v += 256) mx = fmaxf(mx, gen[(size_t)b * V + v]);
    if (tid < TZ) mx = fmaxf(mx, zc[b * TZ + tid] + bz);
    __shared__ float sh[256];
    sh[tid] = mx; __syncthreads();
    for (int s = 128; s > 0; s >>= 1) { if (tid < s) sh[tid] = fmaxf(sh[tid], sh[tid + s]); __syncthreads(); }
    mx = sh[0]; __syncthreads();
    float s = 0.f;
    for (int v = tid; v < V; v += 256) {
        float e = __expf(gen[(size_t)b * V + v] - mx);
        gen[(size_t)b * V + v] = e;
        s += e;
    }
    if (tid < TZ) s += __expf(zc[b * TZ + tid] + bz - mx);
    sh[tid] = s; __syncthreads();
    for (int st = 128; st > 0; st >>= 1) { if (tid < st) sh[tid] += sh[tid + st]; __syncthreads(); }
    s = sh[0];
    if (tid == 0) rsum_inv[b] = 1.f / s;
    if (tid < TZ) cp[b * TZ + tid] = __expf(zc[b * TZ + tid] + bz - mx) / s;
}

__global__ void final_combine(const float* __restrict__ gen,
                              const float* __restrict__ pz,
                              const float* __restrict__ rsum_inv,
                              const float* __restrict__ cp,
                              float* __restrict__ out)
{
    int b = blockIdx.y;
    int v = blockIdx.x * 256 + threadIdx.x;
    __shared__ float cps[TZ];
    __shared__ float inv_s;
    if (threadIdx.x < TZ) cps[threadIdx.x] = cp[b * TZ + threadIdx.x];
    if (threadIdx.x == 0) inv_s = rsum_inv[b];
    __syncthreads();
    float gp = gen[(size_t)b * V + v] * inv_s;
    float acc = 0.f;
#pragma unroll
    for (int t = 0; t < TZ; t++) acc = fmaf(cps[t], pz[(size_t)(t * B + b) * V + v], acc);
    out[(size_t)b * V + v] = gp + (v >= 4 ? acc : 0.f);
}

extern "C" void kernel_launch(void* const* d_in, const int* in_sizes, int n_in,
                              void* d_out, int out_size)
{
    const float* z_enc  = (const float*)d_in[0];
    const float* pz     = (const float*)d_in[1];
    const float* u_enc  = (const float*)d_in[2];
    const int*   mt     = (const int*)  d_in[3];
    const float* h      = (const float*)d_in[4];
    const float* emb    = (const float*)d_in[5];
    const float* Wa_z   = (const float*)d_in[6];
    const float* ba_z   = (const float*)d_in[7];
    const float* v_z    = (const float*)d_in[8];
    const float* Wa_u   = (const float*)d_in[9];
    const float* ba_u   = (const float*)d_in[10];
    const float* v_u    = (const float*)d_in[11];
    const float* W_ih   = (const float*)d_in[12];
    const float* W_hh   = (const float*)d_in[13];
    const float* b_ih   = (const float*)d_in[14];
    const float* b_hh   = (const float*)d_in[15];
    const float* ln_a   = (const float*)d_in[16];
    const float* ln_b   = (const float*)d_in[17];
    const float* W_proj = (const float*)d_in[18];
    const float* b_proj = (const float*)d_in[19];
    const float* W_c    = (const float*)d_in[20];
    const float* b_c    = (const float*)d_in[21];
    const float* W_v1   = (const float*)d_in[22];
    const float* b_v1   = (const float*)d_in[23];
    float* out = (float*)d_out;

    float *hpz, *hpu, *gpart, *sz, *su, *zcb, *cz, *cu, *xb, *gib, *ghb, *grub, *genb, *rsm, *cpb;
    __nv_bfloat16 *uAh, *uAl, *zAh, *zAl, *WuTh, *WuTl, *WzTh, *WzTl, *WcTh, *WcTl;
    cudaGetSymbolAddress((void**)&hpz,  d_hproj_z);
    cudaGetSymbolAddress((void**)&hpu,  d_hproj_u);
    cudaGetSymbolAddress((void**)&gpart,d_gpart);
    cudaGetSymbolAddress((void**)&sz,   d_scores_z);
    cudaGetSymbolAddress((void**)&su,   d_scores_u);
    cudaGetSymbolAddress((void**)&zcb,  d_zc);
    cudaGetSymbolAddress((void**)&cz,   d_ctx_z);
    cudaGetSymbolAddress((void**)&cu,   d_ctx_u);
    cudaGetSymbolAddress((void**)&xb,   d_x);
    cudaGetSymbolAddress((void**)&gib,  d_gi);
    cudaGetSymbolAddress((void**)&ghb,  d_gh);
    cudaGetSymbolAddress((void**)&grub, d_gru);
    cudaGetSymbolAddress((void**)&genb, d_gen);
    cudaGetSymbolAddress((void**)&rsm,  d_rsum);
    cudaGetSymbolAddress((void**)&cpb,  d_cp);
    cudaGetSymbolAddress((void**)&uAh,  d_uAh);
    cudaGetSymbolAddress((void**)&uAl,  d_uAl);
    cudaGetSymbolAddress((void**)&zAh,  d_zAh);
    cudaGetSymbolAddress((void**)&zAl,  d_zAl);
    cudaGetSymbolAddress((void**)&WuTh, d_WuTh);
    cudaGetSymbolAddress((void**)&WuTl, d_WuTl);
    cudaGetSymbolAddress((void**)&WzTh, d_WzTh);
    cudaGetSymbolAddress((void**)&WzTl, d_WzTl);
    cudaGetSymbolAddress((void**)&WcTh, d_WcTh);
    cudaGetSymbolAddress((void**)&WcTl, d_WcTl);

    // 1: zero all accumulators (single launch for deterministic ncu indexing)
    zero_all<<<(B * V + 255) / 256, 256>>>(hpz, hpu, gpart, sz, su, zcb, gib, ghb, genb);
    // 2-5
    split_bf16<<<(TU * B * H + 255) / 256, 256>>>(u_enc, uAh, uAl, TU * B * H);
    split_bf16<<<(TZ * B * H + 255) / 256, 256>>>(z_enc, zAh, zAl, TZ * B * H);
    transpose_split<<<dim3(32, 32), 256>>>(Wa_u + (size_t)H * H, H, WuTh, WuTl);
    small_gemm<true><<<dim3(16, 8), 128>>>(h, H, Wa_u, H, ba_u, hpu, H, 128);
    // 6: the big one (ncu -s 5 -c 1 should land here)
    energy_mma<<<dim3(8, (TU * B) / EBM), 256>>>(uAh, uAl, WuTh, WuTl, hpu, v_u, su, TU);
    // rest
    transpose_split<<<dim3(32, 32), 256>>>(Wa_z + (size_t)H * H, H, WzTh, WzTl);
    transpose_split<<<dim3(32, 32), 256>>>(W_c, H, WcTh, WcTl);
    small_gemm<true><<<dim3(16, 8), 128>>>(h, H, Wa_z, H, ba_z, hpz, H, 128);
    energy_mma<<<dim3(8, (TZ * B) / EBM), 256>>>(zAh, zAl, WzTh, WzTl, hpz, v_z, sz, TZ);

    attn_ctx<<<dim3(B, 4), 256>>>(sz, z_enc, cz, TZ);
    attn_ctx<<<dim3(B, 4), 256>>>(su, u_enc, cu, TU);

    build_x<<<(B * XD + 255) / 256, 256>>>(cz, cu, emb, mt, xb);

    small_gemm<false><<<dim3(48, 5), 128>>>(xb, XD, W_ih, XD, b_ih, gib, G3, 512);
    small_gemm<false><<<dim3(48, 2), 128>>>(h,  H,  W_hh, H,  b_hh, ghb, G3, 512);

    gru_ln<<<B, 1024>>>(gib, ghb, h, ln_a, ln_b, out + (size_t)B * V, grub);

    small_gemm<true><<<dim3(16, 8), 128>>>(grub, H, W_c + (size_t)H * H, H, b_c, gpart, H, 128);
    energy_mma<<<dim3(8, (TZ * B) / EBM), 256>>>(zAh, zAl, WcTh, WcTl, gpart, W_v1, zcb, TZ);

    gen_gemm<<<dim3(V / 128, 4), 128>>>(grub, W_proj, b_proj, genb);

    softmax_stats<<<B, 256>>>(genb, zcb, b_v1, rsm, cpb);
    final_combine<<<dim3(V / 256, B), 256>>>(genb, pz, rsm, cpb, out);

    (void)in_sizes; (void)n_in; (void)out_size;
}

// round 13
// speedup vs baseline: 3.0797x; 1.0991x over previous
#include <cuda_runtime.h>
#include <cuda_fp16.h>
#include <math.h>

#define B   32
#define H   1024
#define TZ  16
#define TU  128
#define E   512
#define V   32000
#define XD  2560
#define G3  3072
#define LN_EPS 1e-3f

__device__ float d_hpz[B*H];
__device__ float d_hpu[B*H];
__device__ float d_gp [B*H];
__device__ float d_sz [B*TZ];
__device__ float d_su [B*TU];
__device__ float d_zcb[B*TZ];
__device__ float d_cz [B*H];
__device__ float d_cu [B*H];
__device__ float d_xb [B*XD];
__device__ float d_gi [B*G3];
__device__ float d_gh [B*G3];
__device__ float d_gru[B*H];
__device__ float d_gen[B*V];
__device__ float d_rs [B];
__device__ float d_cp [B*TZ];
__device__ __align__(16) __half d_uAh[TU*B*H];
__device__ __align__(16) __half d_uAl[TU*B*H];
__device__ __align__(16) __half d_zAh[TZ*B*H];
__device__ __align__(16) __half d_zAl[TZ*B*H];
__device__ __align__(16) __half d_WuT[H*H];
__device__ __align__(16) __half d_WzT[H*H];
__device__ __align__(16) __half d_WcT[H*H];

__device__ __forceinline__ float fast_tanh(float x)
{
    float xc = fminf(fmaxf(x, -7.90531f), 7.90531f);
    float x2 = xc * xc;
    float p = fmaf(x2, -2.76076847742355e-16f, 2.00018790482477e-13f);
    p = fmaf(x2, p, -8.60467152213735e-11f);
    p = fmaf(x2, p,  5.12229709037114e-08f);
    p = fmaf(x2, p,  1.48572235717979e-05f);
    p = fmaf(x2, p,  6.37261928875436e-04f);
    p = fmaf(x2, p,  4.89352455891786e-03f);
    p = xc * p;
    float q = fmaf(x2, 1.19825839466702e-06f, 1.18534705686654e-04f);
    q = fmaf(x2, q, 2.26843463243900e-03f);
    q = fmaf(x2, q, 4.89352518554385e-03f);
    return __fdividef(p, q);
}

__global__ void zero_all()
{
    int i = blockIdx.x * 256 + threadIdx.x;
    if (i < B*H)  { d_hpz[i]=0.f; d_hpu[i]=0.f; d_gp[i]=0.f; }
    if (i < B*TZ) { d_sz[i]=0.f; d_zcb[i]=0.f; }
    if (i < B*TU) d_su[i]=0.f;
    if (i < B*G3) { d_gi[i]=0.f; d_gh[i]=0.f; }
    if (i < B*V)  d_gen[i]=0.f;
}

__global__ void split_f16(const float* __restrict__ x, int mode, int n)
{
    int i = blockIdx.x * 256 + threadIdx.x;
    if (i >= n) return;
    __half* hi = mode ? d_zAh : d_uAh;
    __half* lo = mode ? d_zAl : d_uAl;
    float v = x[i];
    __half h = __float2half(v);
    hi[i] = h;
    lo[i] = __float2half(v - __half2float(h));
}

// W[k][n] (ld=H) -> T[n][k] single fp16
__global__ void transpose_f16(const float* __restrict__ W, int mode)
{
    __shared__ float tile[32][33];
    __half* Th = (mode==0) ? d_WuT : ((mode==1) ? d_WzT : d_WcT);
    int k0 = blockIdx.x * 32, n0 = blockIdx.y * 32;
    int tx = threadIdx.x & 31, ty = threadIdx.x >> 5;
    for (int i = ty; i < 32; i += 8)
        tile[i][tx] = W[(size_t)(k0 + i) * H + n0 + tx];
    __syncthreads();
    for (int i = ty; i < 32; i += 8)
        Th[(size_t)(n0 + i) * H + k0 + tx] = __float2half(tile[tx][i]);
}

__device__ __forceinline__ void mma16816(float* c, const unsigned* a, const unsigned* b)
{
    asm volatile(
        "mma.sync.aligned.m16n8k16.row.col.f32.f16.f16.f32 "
        "{%0,%1,%2,%3}, {%4,%5,%6,%7}, {%8,%9}, {%0,%1,%2,%3};"
        : "+f"(c[0]), "+f"(c[1]), "+f"(c[2]), "+f"(c[3])
        : "r"(a[0]), "r"(a[1]), "r"(a[2]), "r"(a[3]), "r"(b[0]), "r"(b[1]));
}

__device__ __forceinline__ void ldsm_x4(unsigned* r, const void* p)
{
    unsigned a = (unsigned)__cvta_generic_to_shared(p);
    asm volatile("ldmatrix.sync.aligned.m8n8.x4.shared.b16 {%0,%1,%2,%3}, [%4];"
        : "=r"(r[0]), "=r"(r[1]), "=r"(r[2]), "=r"(r[3]) : "r"(a));
}

__device__ __forceinline__ void cp16(void* s, const void* g)
{
    unsigned sa = (unsigned)__cvta_generic_to_shared(s);
    asm volatile("cp.async.cg.shared.global [%0], [%1], 16;\n" :: "r"(sa), "l"(g));
}
__device__ __forceinline__ void cp_commit() { asm volatile("cp.async.commit_group;\n"); }
template<int N> __device__ __forceinline__ void cp_wait() {
    asm volatile("cp.async.wait_group %0;\n" :: "n"(N));
}

// scores[b,t] += sum_n tanh((A@Wt^T)[r,n] + addv[b,n]) * v[n] ; r=t*B+b
// A split (hi+lo fp16), W single fp16. 2 MMAs per fragment. double-buffered.
#define EBM 64
#define EBN 128
#define SKW 20
__global__ void __launch_bounds__(256, 2)
energy_mma(int mode, const float* __restrict__ vvec, int T)
{
    const __half* Ah = (mode==0) ? d_uAh : d_zAh;
    const __half* Al = (mode==0) ? d_uAl : d_zAl;
    const __half* Wh = (mode==0) ? d_WuT : ((mode==1) ? d_WzT : d_WcT);
    const float* addv = (mode==0) ? d_hpu : ((mode==1) ? d_hpz : d_gp);
    float* outp = (mode==0) ? d_su : ((mode==1) ? d_sz : d_zcb);

    __shared__ __align__(16) unsigned sAh[2][EBM * SKW], sAl[2][EBM * SKW];
    __shared__ __align__(16) unsigned sB[2][EBN * SKW];
    int tid = threadIdx.x, wid = tid >> 5, lane = tid & 31;
    int wm = wid >> 2, wn = wid & 3;
    int row0 = blockIdx.y * EBM, col0 = blockIdx.x * EBN;
    int l4 = lane >> 2, lm = lane & 3, lane7 = lane & 7;

    int idxA = (wm * 32 + lane7 + ((lane >> 3) & 1) * 8) * SKW + ((lane >> 4) & 1) * 4;
    int idxB = (wn * 32 + lane7 + ((lane >> 4) & 1) * 8) * SKW + ((lane >> 3) & 1) * 4;

    float c[2][4][4];
#pragma unroll
    for (int mt = 0; mt < 2; mt++)
#pragma unroll
        for (int nt = 0; nt < 4; nt++)
#pragma unroll
            for (int e = 0; e < 4; e++) c[mt][nt][e] = 0.f;

    for (int i = tid; i < EBM * 4; i += 256) {
        int m = i >> 2, q = i & 3;
        size_t off = (size_t)(row0 + m) * H + q * 8;
        cp16(&sAh[0][m * SKW + q * 4], Ah + off);
        cp16(&sAl[0][m * SKW + q * 4], Al + off);
    }
    for (int i = tid; i < EBN * 4; i += 256) {
        int n = i >> 2, q = i & 3;
        cp16(&sB[0][n * SKW + q * 4], Wh + (size_t)(col0 + n) * H + q * 8);
    }
    cp_commit();

    const int NC = H / 32;
    for (int kc = 0; kc < NC; kc++) {
        int p = kc & 1;
        if (kc + 1 < NC) {
            int k1 = (kc + 1) * 32;
            for (int i = tid; i < EBM * 4; i += 256) {
                int m = i >> 2, q = i & 3;
                size_t off = (size_t)(row0 + m) * H + k1 + q * 8;
                cp16(&sAh[p ^ 1][m * SKW + q * 4], Ah + off);
                cp16(&sAl[p ^ 1][m * SKW + q * 4], Al + off);
            }
            for (int i = tid; i < EBN * 4; i += 256) {
                int n = i >> 2, q = i & 3;
                cp16(&sB[p ^ 1][n * SKW + q * 4], Wh + (size_t)(col0 + n) * H + k1 + q * 8);
            }
            cp_commit();
            cp_wait<1>();
        } else {
            cp_wait<0>();
        }
        __syncthreads();
#pragma unroll
        for (int ks = 0; ks < 2; ks++) {
            int ko = ks * 8;
            unsigned ah[2][4], al[2][4], bh2[2][4];
            ldsm_x4(ah[0],  &sAh[p][idxA + ko]);
            ldsm_x4(ah[1],  &sAh[p][idxA + 16 * SKW + ko]);
            ldsm_x4(al[0],  &sAl[p][idxA + ko]);
            ldsm_x4(al[1],  &sAl[p][idxA + 16 * SKW + ko]);
            ldsm_x4(bh2[0], &sB[p][idxB + ko]);
            ldsm_x4(bh2[1], &sB[p][idxB + 16 * SKW + ko]);
#pragma unroll
            for (int nt = 0; nt < 4; nt++) {
                const unsigned* bh = &bh2[nt >> 1][(nt & 1) * 2];
#pragma unroll
                for (int mt = 0; mt < 2; mt++) {
                    mma16816(c[mt][nt], ah[mt], bh);
                    mma16816(c[mt][nt], al[mt], bh);
                }
            }
        }
        __syncthreads();
    }
#pragma unroll
    for (int mt = 0; mt < 2; mt++)
#pragma unroll
        for (int half = 0; half < 2; half++) {
            int row = row0 + wm * 32 + mt * 16 + l4 + half * 8;
            int b = row & 31, t = row >> 5;
            float s = 0.f;
#pragma unroll
            for (int nt = 0; nt < 4; nt++) {
                int n0 = col0 + wn * 32 + nt * 8 + lm * 2;
                float e0 = fast_tanh(c[mt][nt][half * 2 + 0] + addv[b * H + n0]);
                float e1 = fast_tanh(c[mt][nt][half * 2 + 1] + addv[b * H + n0 + 1]);
                s = fmaf(e0, vvec[n0], s);
                s = fmaf(e1, vvec[n0 + 1], s);
            }
            s += __shfl_xor_sync(0xffffffff, s, 1);
            s += __shfl_xor_sync(0xffffffff, s, 2);
            if (lm == 0) atomicAdd(&outp[b * T + t], s);
        }
}

// out[b][j] += sum_k x[b][k]*W(k,j) (+bias on y==0). KMAJOR: W[k*ldw+j], else W[j*ldw+k].
template<bool KMAJOR>
__global__ void __launch_bounds__(128)
small_gemm(const float* __restrict__ xpar, int ldx,
           const float* __restrict__ W, int ldw,
           const float* __restrict__ bias, int osel, int N, int kchunk)
{
    __shared__ float xs[32][33];
    __shared__ float Ws[32 * 65];
    const float* x = (osel==2) ? d_xb : ((osel==4) ? d_gru : xpar);
    float* out = (osel==0) ? d_hpz : ((osel==1) ? d_hpu : ((osel==2) ? d_gi : ((osel==3) ? d_gh : d_gp)));
    int tid = threadIdx.x, tj = tid & 15, tb = tid >> 4;
    int j0 = blockIdx.x * 64;
    int kbeg = blockIdx.y * kchunk, kend = kbeg + kchunk;
    float acc[4][4] = {};
    for (int k0 = kbeg; k0 < kend; k0 += 32) {
        for (int i = tid; i < 256; i += 128) {
            int bb = i >> 3, q = i & 7;
            float4 vv = *(const float4*)&x[(size_t)bb * ldx + k0 + q * 4];
            xs[bb][q * 4 + 0] = vv.x; xs[bb][q * 4 + 1] = vv.y;
            xs[bb][q * 4 + 2] = vv.z; xs[bb][q * 4 + 3] = vv.w;
        }
        if (KMAJOR) {
            for (int i = tid; i < 512; i += 128) {
                int kk = i >> 4, jq = i & 15;
                float4 vv = *(const float4*)&W[(size_t)(k0 + kk) * ldw + j0 + jq * 4];
                Ws[kk * 65 + jq * 4 + 0] = vv.x; Ws[kk * 65 + jq * 4 + 1] = vv.y;
                Ws[kk * 65 + jq * 4 + 2] = vv.z; Ws[kk * 65 + jq * 4 + 3] = vv.w;
            }
        } else {
            for (int i = tid; i < 512; i += 128) {
                int j = i >> 3, q = i & 7;
                float4 vv = *(const float4*)&W[(size_t)(j0 + j) * ldw + k0 + q * 4];
                Ws[(q * 4 + 0) * 65 + j] = vv.x; Ws[(q * 4 + 1) * 65 + j] = vv.y;
                Ws[(q * 4 + 2) * 65 + j] = vv.z; Ws[(q * 4 + 3) * 65 + j] = vv.w;
            }
        }
        __syncthreads();
#pragma unroll 8
        for (int kk = 0; kk < 32; kk++) {
            float a[4], w[4];
#pragma unroll
            for (int i = 0; i < 4; i++) a[i] = xs[tb * 4 + i][kk];
#pragma unroll
            for (int j = 0; j < 4; j++) w[j] = Ws[kk * 65 + tj * 4 + j];
#pragma unroll
            for (int i = 0; i < 4; i++)
#pragma unroll
                for (int j = 0; j < 4; j++) acc[i][j] = fmaf(a[i], w[j], acc[i][j]);
        }
        __syncthreads();
    }
#pragma unroll
    for (int i = 0; i < 4; i++)
#pragma unroll
        for (int j = 0; j < 4; j++) {
            int jj = j0 + tj * 4 + j;
            float v = acc[i][j] + ((blockIdx.y == 0) ? bias[jj] : 0.f);
            atomicAdd(&out[(tb * 4 + i) * N + jj], v);
        }
}

__global__ void attn_ctx(int mode, const float* __restrict__ enc, int T)
{
    const float* scores = mode ? d_su : d_sz;
    float* ctx = mode ? d_cu : d_cz;
    int b = blockIdx.x, tid = threadIdx.x;
    __shared__ float w[TU];
    __shared__ float inv_s;
    if (tid < 32) {
        float m = -1e30f;
        for (int t = tid; t < T; t += 32) m = fmaxf(m, scores[b * T + t]);
#pragma unroll
        for (int o = 16; o > 0; o >>= 1) m = fmaxf(m, __shfl_xor_sync(0xffffffff, m, o));
        float s = 0.f;
        for (int t = tid; t < T; t += 32) {
            float e = __expf(scores[b * T + t] - m);
            w[t] = e; s += e;
        }
#pragma unroll
        for (int o = 16; o > 0; o >>= 1) s += __shfl_xor_sync(0xffffffff, s, o);
        if (tid == 0) inv_s = 1.f / s;
    }
    __syncthreads();
    int j = blockIdx.y * 256 + tid;
    float acc = 0.f;
    for (int t = 0; t < T; t++) acc = fmaf(w[t], enc[(size_t)(t * B + b) * H + j], acc);
    ctx[b * H + j] = acc * inv_s;
}

__global__ void build_x(const float* __restrict__ emb, const int* __restrict__ mt)
{
    int idx = blockIdx.x * 256 + threadIdx.x;
    if (idx >= B * XD) return;
    int b = idx / XD, k = idx % XD;
    float vl;
    if (k < H)           vl = d_cz[b * H + k];
    else if (k < 2 * H)  vl = d_cu[b * H + (k - H)];
    else                 vl = emb[(size_t)mt[b] * E + (k - 2 * H)];
    d_xb[idx] = vl;
}

__global__ void gru_ln(const float* __restrict__ h,
                       const float* __restrict__ lna, const float* __restrict__ lnb,
                       float* __restrict__ hnew_out)
{
    int b = blockIdx.x, j = threadIdx.x;
    float ir = d_gi[b*G3+j], iz = d_gi[b*G3+H+j], inn = d_gi[b*G3+2*H+j];
    float hr = d_gh[b*G3+j], hz = d_gh[b*G3+H+j], hn  = d_gh[b*G3+2*H+j];
    float r  = 1.f / (1.f + __expf(-(ir + hr)));
    float zg = 1.f / (1.f + __expf(-(iz + hz)));
    float n  = fast_tanh(inn + r * hn);
    float hv = h[b * H + j];
    float hnew = (1.f - zg) * n + zg * hv;
    hnew_out[b * H + j] = hnew;
    __shared__ float sh[1024];
    sh[j] = hnew; __syncthreads();
    for (int s = 512; s > 0; s >>= 1) { if (j < s) sh[j] += sh[j + s]; __syncthreads(); }
    float mu = sh[0] * (1.f / H); __syncthreads();
    float d = hnew - mu;
    sh[j] = d * d; __syncthreads();
    for (int s = 512; s > 0; s >>= 1) { if (j < s) sh[j] += sh[j + s]; __syncthreads(); }
    float sigma = sqrtf(sh[0] / (float)(H - 1));
    d_gru[b * H + j] = d / (sigma + LN_EPS) * lna[j] + lnb[j];
}

__global__ void __launch_bounds__(128)
gen_gemm(const float* __restrict__ Wp, const float* __restrict__ bproj)
{
    __shared__ float gs[32][65];
    int tid = threadIdx.x, tv = tid & 31, tb = tid >> 5;
    int v0 = blockIdx.x * 128 + tv * 4;
    int b0 = tb * 8;
    int kbeg = blockIdx.y * 256;
    float acc[8][4] = {};
    for (int kb = 0; kb < 256; kb += 64) {
        for (int i = tid; i < 512; i += 128) {
            int bb = i >> 4, q = i & 15;
            float4 vv = *(const float4*)&d_gru[(size_t)bb * H + kbeg + kb + q * 4];
            gs[bb][q * 4 + 0] = vv.x; gs[bb][q * 4 + 1] = vv.y;
            gs[bb][q * 4 + 2] = vv.z; gs[bb][q * 4 + 3] = vv.w;
        }
        __syncthreads();
#pragma unroll 4
        for (int kk = 0; kk < 64; kk++) {
            float4 w = *(const float4*)&Wp[(size_t)(kbeg + kb + kk) * V + v0];
            float a[8];
#pragma unroll
            for (int i = 0; i < 8; i++) a[i] = gs[b0 + i][kk];
#pragma unroll
            for (int i = 0; i < 8; i++) {
                acc[i][0] = fmaf(a[i], w.x, acc[i][0]);
                acc[i][1] = fmaf(a[i], w.y, acc[i][1]);
                acc[i][2] = fmaf(a[i], w.z, acc[i][2]);
                acc[i][3] = fmaf(a[i], w.w, acc[i][3]);
            }
        }
        __syncthreads();
    }
#pragma unroll
    for (int i = 0; i < 8; i++)
#pragma unroll
        for (int j = 0; j < 4; j++) {
            float v = acc[i][j] + ((blockIdx.y == 0) ? bproj[v0 + j] : 0.f);
            atomicAdd(&d_gen[(size_t)(b0 + i) * V + v0 + j], v);
        }
}

__global__ void softmax_stats(const float* __restrict__ bv1)
{
    int b = blockIdx.x, tid = threadIdx.x;
    float bz = bv1[0];
    float mx = -1e30f;
    for (int v = tid; v < V; v += 256) mx = fmaxf(mx, d_gen[(size_t)b * V + v]);
    if (tid < TZ) mx = fmaxf(mx, d_zcb[b * TZ + tid] + bz);
    __shared__ float sh[256];
    sh[tid] = mx; __syncthreads();
    for (int s = 128; s > 0; s >>= 1) { if (tid < s) sh[tid] = fmaxf(sh[tid], sh[tid + s]); __syncthreads(); }
    mx = sh[0]; __syncthreads();
    float s = 0.f;
    for (int v = tid; v < V; v += 256) {
        float e = __expf(d_gen[(size_t)b * V + v] - mx);
        d_gen[(size_t)b * V + v] = e;
        s += e;
    }
    if (tid < TZ) s += __expf(d_zcb[b * TZ + tid] + bz - mx);
    sh[tid] = s; __syncthreads();
    for (int st = 128; st > 0; st >>= 1) { if (tid < st) sh[tid] += sh[tid + st]; __syncthreads(); }
    s = sh[0];
    if (tid == 0) d_rs[b] = 1.f / s;
    if (tid < TZ) d_cp[b * TZ + tid] = __expf(d_zcb[b * TZ + tid] + bz - mx) / s;
}

__global__ void final_combine(const float* __restrict__ pz, float* __restrict__ out)
{
    int b = blockIdx.y;
    int v = blockIdx.x * 256 + threadIdx.x;
    __shared__ float cps[TZ];
    __shared__ float inv_s;
    if (threadIdx.x < TZ) cps[threadIdx.x] = d_cp[b * TZ + threadIdx.x];
    if (threadIdx.x == 0) inv_s = d_rs[b];
    __syncthreads();
    float gp = d_gen[(size_t)b * V + v] * inv_s;
    float acc = 0.f;
#pragma unroll
    for (int t = 0; t < TZ; t++) acc = fmaf(cps[t], pz[(size_t)(t * B + b) * V + v], acc);
    out[(size_t)b * V + v] = gp + (v >= 4 ? acc : 0.f);
}

extern "C" void kernel_launch(void* const* d_in, const int* in_sizes, int n_in,
                              void* d_out, int out_size)
{
    const float* z_enc = (const float*)d_in[0];
    const float* pz    = (const float*)d_in[1];
    const float* u_enc = (const float*)d_in[2];
    const int*   mt    = (const int*)d_in[3];
    const float* h     = (const float*)d_in[4];
    const float* emb   = (const float*)d_in[5];
    const float* Wa_z  = (const float*)d_in[6];
    const float* ba_z  = (const float*)d_in[7];
    const float* v_z   = (const float*)d_in[8];
    const float* Wa_u  = (const float*)d_in[9];
    const float* ba_u  = (const float*)d_in[10];
    const float* v_u   = (const float*)d_in[11];
    const float* W_ih  = (const float*)d_in[12];
    const float* W_hh  = (const float*)d_in[13];
    const float* b_ih  = (const float*)d_in[14];
    const float* b_hh  = (const float*)d_in[15];
    const float* ln_a  = (const float*)d_in[16];
    const float* ln_b  = (const float*)d_in[17];
    const float* W_pj  = (const float*)d_in[18];
    const float* b_pj  = (const float*)d_in[19];
    const float* W_c   = (const float*)d_in[20];
    const float* b_c   = (const float*)d_in[21];
    const float* W_v1  = (const float*)d_in[22];
    const float* b_v1  = (const float*)d_in[23];
    float* out = (float*)d_out;

    zero_all<<<(B*V + 255) / 256, 256>>>();
    split_f16<<<(TU*B*H + 255) / 256, 256>>>(u_enc, 0, TU*B*H);
    split_f16<<<(TZ*B*H + 255) / 256, 256>>>(z_enc, 1, TZ*B*H);
    transpose_f16<<<dim3(32, 32), 256>>>(Wa_u + (size_t)H*H, 0);
    small_gemm<true><<<dim3(16, 8), 128>>>(h, H, Wa_u, H, ba_u, 1, H, 128);
    energy_mma<<<dim3(8, (TU*B) / EBM), 256>>>(0, v_u, TU);
    transpose_f16<<<dim3(32, 32), 256>>>(Wa_z + (size_t)H*H, 1);
    transpose_f16<<<dim3(32, 32), 256>>>(W_c, 2);
    small_gemm<true><<<dim3(16, 8), 128>>>(h, H, Wa_z, H, ba_z, 0, H, 128);
    energy_mma<<<dim3(8, (TZ*B) / EBM), 256>>>(1, v_z, TZ);
    attn_ctx<<<dim3(B, 4), 256>>>(0, z_enc, TZ);
    attn_ctx<<<dim3(B, 4), 256>>>(1, u_enc, TU);
    build_x<<<(B*XD + 255) / 256, 256>>>(emb, mt);
    small_gemm<false><<<dim3(48, 5), 128>>>(h, XD, W_ih, XD, b_ih, 2, G3, 512);
    small_gemm<false><<<dim3(48, 2), 128>>>(h, H, W_hh, H, b_hh, 3, G3, 512);
    gru_ln<<<B, 1024>>>(h, ln_a, ln_b, out + (size_t)B*V);
    small_gemm<true><<<dim3(16, 8), 128>>>(h, H, W_c + (size_t)H*H, H, b_c, 4, H, 128);
    energy_mma<<<dim3(8, (TZ*B) / EBM), 256>>>(2, W_v1, TZ);
    gen_gemm<<<dim3(V / 128, 4), 128>>>(W_pj, b_pj);
    softmax_stats<<<B, 256>>>(b_v1);
    final_combine<<<dim3(V / 256, B), 256>>>(pz, out);

    (void)in_sizes; (void)n_in; (void)out_size;
}